// round 1
// baseline (speedup 1.0000x reference)
#include <cuda_runtime.h>
#include <math.h>

#define T_LEN   8192
#define B_SZ    2
#define N_HEADS 8
#define DH      128
#define EMB     1024
#define BHD     16          // B * HEADS
#define N_HASH  8
#define NB      128         // buckets per hash
#define NBTOT   1024        // N_HASH * NB
#define BUCKETSZ 64
#define NCHUNK  1024        // per bh
#define HT      65536       // N_HASH * T
#define BT      16384       // B * T
#define QSCALE  0.08838834764831843f

// ----------------------------- scratch (static device memory; no allocs) ---
__device__ float g_qk[(size_t)BT * EMB];            // 67 MB
__device__ float g_v[(size_t)BT * EMB];             // 67 MB
__device__ float g_rv[(size_t)BHD * T_LEN * 512];   // 268 MB
__device__ int   g_buckets[(size_t)BHD * HT];       // 4 MB
__device__ int   g_counts[BHD * NBTOT];
__device__ int   g_offsets[BHD * NBTOT];
__device__ int   g_st[(size_t)BHD * HT];            // token pos at sorted slot
__device__ int   g_undo[(size_t)BHD * HT];          // sorted slot of (h,pos)
__device__ float g_so[(size_t)BHD * HT * DH];       // 536 MB
__device__ float g_slog[(size_t)BHD * HT];
__device__ float g_attn[(size_t)BT * EMB];          // 67 MB

// ----------------------------- generic tiled fp32 GEMM ---------------------
// C[z] = A[z] @ B (+bias), row-major. Batch offset: (z/innerDiv)*sAouter + (z%innerDiv)*sAinner.
#define BM 64
#define BN 64
#define BKK 16

__global__ void gemm_kernel(const float* __restrict__ A, const float* __restrict__ Bm,
                            float* __restrict__ C, const float* __restrict__ bias,
                            int M, int N, int K, int lda, int ldb, int ldc,
                            long long sAouter, long long sAinner, int innerDiv,
                            long long sC)
{
    __shared__ float As[BKK][BM + 1];
    __shared__ float Bs[BKK][BN];
    int z = blockIdx.z;
    const float* Ab = A + (long long)(z / innerDiv) * sAouter + (long long)(z % innerDiv) * sAinner;
    float* Cb = C + (long long)z * sC;
    int row0 = blockIdx.y * BM;
    int col0 = blockIdx.x * BN;
    int tid = threadIdx.x;
    int tx = tid & 15, ty = tid >> 4;
    float acc[4][4];
#pragma unroll
    for (int i = 0; i < 4; i++)
#pragma unroll
        for (int j = 0; j < 4; j++) acc[i][j] = 0.f;

    for (int k0 = 0; k0 < K; k0 += BKK) {
#pragma unroll
        for (int i = 0; i < 4; i++) {
            int e = tid + 256 * i;                 // 1024 elems of A tile (64x16)
            int r = e >> 4, kk = e & 15;
            As[kk][r] = __ldg(&Ab[(size_t)(row0 + r) * lda + k0 + kk]);
        }
#pragma unroll
        for (int i = 0; i < 4; i++) {
            int e = tid + 256 * i;                 // 1024 elems of B tile (16x64)
            int kk = e >> 6, c = e & 63;
            Bs[kk][c] = __ldg(&Bm[(size_t)(k0 + kk) * ldb + col0 + c]);
        }
        __syncthreads();
#pragma unroll
        for (int kk = 0; kk < BKK; kk++) {
            float a[4], bb[4];
#pragma unroll
            for (int i = 0; i < 4; i++) a[i] = As[kk][ty * 4 + i];
#pragma unroll
            for (int i = 0; i < 4; i++) bb[i] = Bs[kk][tx * 4 + i];
#pragma unroll
            for (int i = 0; i < 4; i++)
#pragma unroll
                for (int j = 0; j < 4; j++) acc[i][j] = fmaf(a[i], bb[j], acc[i][j]);
        }
        __syncthreads();
    }
#pragma unroll
    for (int i = 0; i < 4; i++) {
        int r = row0 + ty * 4 + i;
#pragma unroll
        for (int j = 0; j < 4; j++) {
            int c = col0 + tx * 4 + j;
            float o = acc[i][j];
            if (bias) o += bias[c];
            Cb[(size_t)r * ldc + c] = o;
        }
    }
}

// ----------------------------- bucket argmax --------------------------------
__global__ void bucket_kernel()
{
    int idx = blockIdx.x * 256 + threadIdx.x;          // BHD*HT threads
    int t = idx & (T_LEN - 1);
    int h = (idx >> 13) & (N_HASH - 1);
    int bh = idx >> 16;
    const float* rv = g_rv + ((size_t)bh * T_LEN + t) * 512 + h * 64;
    float best = rv[0];
    int bi = 0;
#pragma unroll 4
    for (int j = 1; j < 64; j++) { float v = rv[j]; if (v > best) { best = v; bi = j; } }
#pragma unroll 4
    for (int j = 0; j < 64; j++) { float v = -rv[j]; if (v > best) { best = v; bi = 64 + j; } }
    g_buckets[idx] = bi + h * NB;
}

__global__ void zero_counts_kernel()
{
    int idx = blockIdx.x * 256 + threadIdx.x;
    if (idx < BHD * NBTOT) g_counts[idx] = 0;
}

__global__ void hist_kernel()
{
    int idx = blockIdx.x * 256 + threadIdx.x;          // BHD*HT
    int bh = idx >> 16;
    atomicAdd(&g_counts[bh * NBTOT + g_buckets[idx]], 1);
}

__global__ void scan_kernel()
{
    __shared__ int s[NBTOT];
    int bh = blockIdx.x, t = threadIdx.x;
    int my = g_counts[bh * NBTOT + t];
    s[t] = my;
    __syncthreads();
    for (int d = 1; d < NBTOT; d <<= 1) {
        int v = (t >= d) ? s[t - d] : 0;
        __syncthreads();
        s[t] += v;
        __syncthreads();
    }
    g_offsets[bh * NBTOT + t] = s[t] - my;             // exclusive prefix
}

// stable scatter: one warp per (bh, hash, local bucket)
__global__ void scatter_kernel()
{
    int gw = (blockIdx.x * 256 + threadIdx.x) >> 5;    // 0..BHD*N_HASH*NB-1
    int lane = threadIdx.x & 31;
    int lb = gw & (NB - 1);
    int h = (gw >> 7) & (N_HASH - 1);
    int bh = gw >> 10;
    int gb = h * NB + lb;
    int base = g_offsets[bh * NBTOT + gb];
    const int* bk = g_buckets + (size_t)bh * HT + (size_t)h * T_LEN;
    for (int t0 = 0; t0 < T_LEN; t0 += 32) {
        int t = t0 + lane;
        int bv = bk[t];
        unsigned mask = __ballot_sync(0xffffffffu, bv == gb);
        if (bv == gb) {
            int rnk = base + __popc(mask & ((1u << lane) - 1u));
            g_st[(size_t)bh * HT + rnk] = t;
            g_undo[(size_t)bh * HT + (size_t)h * T_LEN + t] = rnk;
        }
        base += __popc(mask);
    }
}

// ----------------------------- chunked attention ----------------------------
// smem (floats): qT[128][65] | ks[128][129] | vs[128][129] | scb[8256] | red[256] | posk[128] padk[128]
#define SMEM_ATT ((8320 + 16512 + 16512 + 8256 + 256) * 4 + 256 * 4)

__global__ void attn_kernel(const unsigned char* __restrict__ pm)
{
    extern __shared__ float smem[];
    float* qT  = smem;                       // pitch 65
    float* ks  = qT + 8320;                  // pitch 129
    float* vs  = ks + 16512;                 // pitch 129
    float* scb = vs + 16512;                 // [j][r] pitch 64, later [r][d] pitch 129
    float* red = scb + 8256;                 // 4 x 64
    int* posk = (int*)(red + 256);
    int* padk = posk + 128;

    int bh = blockIdx.y, c = blockIdx.x;
    int b = bh >> 3, h = bh & 7;
    int tid = threadIdx.x, lane = tid & 31, w = tid >> 5;

    // phase 0: slot -> token positions + pad flags
    if (tid < 128) {
        int j = tid;
        int cprev = (c == 0) ? (NCHUNK - 1) : (c - 1);
        int slot = (j < BUCKETSZ) ? c * BUCKETSZ + j : cprev * BUCKETSZ + (j - BUCKETSZ);
        int pos = g_st[(size_t)bh * HT + slot];
        posk[j] = pos;
        padk[j] = pm[b * T_LEN + pos] ? 1 : 0;
    }
    __syncthreads();

    // phase 1: load q (scaled, transposed), k (l2-normalized), v
    for (int rr = 0; rr < 8; rr++) {
        int r = w * 8 + rr;
        int pos = posk[r];
        const float* src = g_qk + ((size_t)(b * T_LEN + pos)) * EMB + h * DH;
#pragma unroll
        for (int kk = 0; kk < 4; kk++) {
            int f = lane + 32 * kk;
            qT[f * 65 + r] = src[f] * QSCALE;
        }
    }
    for (int jj = 0; jj < 16; jj++) {
        int j = w * 16 + jj;
        int pos = posk[j];
        const float* src = g_qk + ((size_t)(b * T_LEN + pos)) * EMB + h * DH;
        float v0[4]; float ss = 0.f;
#pragma unroll
        for (int kk = 0; kk < 4; kk++) { v0[kk] = src[lane + 32 * kk]; ss += v0[kk] * v0[kk]; }
#pragma unroll
        for (int o = 16; o > 0; o >>= 1) ss += __shfl_xor_sync(0xffffffffu, ss, o);
        float rn = rsqrtf(fmaxf(ss, 1e-12f));
#pragma unroll
        for (int kk = 0; kk < 4; kk++) ks[j * 129 + lane + 32 * kk] = v0[kk] * rn;
        const float* sv = g_v + ((size_t)(b * T_LEN + pos)) * EMB + h * DH;
#pragma unroll
        for (int kk = 0; kk < 4; kk++) vs[j * 129 + lane + 32 * kk] = sv[lane + 32 * kk];
    }
    __syncthreads();

    // phase 2: scores (4 rows x 8 cols per thread)
    int rsub = tid & 15;
    int j0 = (tid >> 4) * 8;
    {
        float acc[4][8];
#pragma unroll
        for (int i = 0; i < 4; i++)
#pragma unroll
            for (int j = 0; j < 8; j++) acc[i][j] = 0.f;
#pragma unroll 4
        for (int f = 0; f < 128; f++) {
            float qv[4];
#pragma unroll
            for (int ri = 0; ri < 4; ri++) qv[ri] = qT[f * 65 + rsub + 16 * ri];
#pragma unroll
            for (int ji = 0; ji < 8; ji++) {
                float kv = ks[(j0 + ji) * 129 + f];
#pragma unroll
                for (int ri = 0; ri < 4; ri++) acc[ri][ji] = fmaf(qv[ri], kv, acc[ri][ji]);
            }
        }
#pragma unroll
        for (int ri = 0; ri < 4; ri++) {
            int r = rsub + 16 * ri;
            int pq = posk[r];
#pragma unroll
            for (int ji = 0; ji < 8; ji++) {
                int j = j0 + ji;
                float s = acc[ri][ji];
                if (pq == posk[j]) s = -1e5f;
                else if (padk[j]) s = -1e9f;
                scb[j * 64 + r] = s;
            }
        }
    }
    __syncthreads();

    // phase 3: exact softmax (4 threads per row)
    {
        int r = tid & 63, q4 = tid >> 6;
        float m = -1e30f;
        for (int jj = 0; jj < 32; jj++) m = fmaxf(m, scb[(q4 * 32 + jj) * 64 + r]);
        red[q4 * 64 + r] = m;
        __syncthreads();
        float M = fmaxf(fmaxf(red[r], red[64 + r]), fmaxf(red[128 + r], red[192 + r]));
        float ssum = 0.f;
        for (int jj = 0; jj < 32; jj++) ssum += expf(scb[(q4 * 32 + jj) * 64 + r] - M);
        __syncthreads();
        red[q4 * 64 + r] = ssum;
        __syncthreads();
        float Z = red[r] + red[64 + r] + red[128 + r] + red[192 + r];
        float lse = M + logf(Z);
        if (q4 == 0) g_slog[(size_t)bh * HT + c * BUCKETSZ + r] = lse;
        for (int jj = 0; jj < 32; jj++) {
            int j = q4 * 32 + jj;
            scb[j * 64 + r] = expf(scb[j * 64 + r] - lse);
        }
    }
    __syncthreads();

    // phase 4: out = probs @ v  (4 rows x 8 d per thread)
    {
        int d0 = (tid >> 4) * 8;
        float a2[4][8];
#pragma unroll
        for (int i = 0; i < 4; i++)
#pragma unroll
            for (int j = 0; j < 8; j++) a2[i][j] = 0.f;
#pragma unroll 4
        for (int kv = 0; kv < 128; kv++) {
            float pv[4];
#pragma unroll
            for (int ri = 0; ri < 4; ri++) pv[ri] = scb[kv * 64 + rsub + 16 * ri];
#pragma unroll
            for (int di = 0; di < 8; di++) {
                float vv = vs[kv * 129 + d0 + di];
#pragma unroll
                for (int ri = 0; ri < 4; ri++) a2[ri][di] = fmaf(pv[ri], vv, a2[ri][di]);
            }
        }
        __syncthreads();   // all prob reads done; reuse scb as out staging [r][129]
#pragma unroll
        for (int ri = 0; ri < 4; ri++) {
            int r = rsub + 16 * ri;
#pragma unroll
            for (int di = 0; di < 8; di++) scb[r * 129 + d0 + di] = a2[ri][di];
        }
    }
    __syncthreads();

    // coalesced global write of chunk output
    for (int rr = 0; rr < 8; rr++) {
        int r = w * 8 + rr;
        float* dst = g_so + ((size_t)bh * HT + c * BUCKETSZ + r) * DH;
#pragma unroll
        for (int kk = 0; kk < 4; kk++) {
            int d = lane + 32 * kk;
            dst[d] = scb[r * 129 + d];
        }
    }
}

// ----------------------------- combine hash rounds --------------------------
__global__ void combine_kernel()
{
    int gw = (blockIdx.x * 256 + threadIdx.x) >> 5;    // 0..BHD*T-1
    int lane = threadIdx.x & 31;
    int bh = gw >> 13;
    int pos = gw & (T_LEN - 1);
    int b = bh >> 3, hh = bh & 7;

    int s = 0;
    float l = -1e30f;
    if (lane < N_HASH) {
        s = g_undo[(size_t)bh * HT + (size_t)lane * T_LEN + pos];
        l = g_slog[(size_t)bh * HT + s];
    }
    float m = l;
#pragma unroll
    for (int o = 16; o > 0; o >>= 1) m = fmaxf(m, __shfl_xor_sync(0xffffffffu, m, o));
    float e = (lane < N_HASH) ? expf(l - m) : 0.f;
    float Z = e;
#pragma unroll
    for (int o = 16; o > 0; o >>= 1) Z += __shfl_xor_sync(0xffffffffu, Z, o);

    float4 acc = make_float4(0.f, 0.f, 0.f, 0.f);
#pragma unroll
    for (int h2 = 0; h2 < N_HASH; h2++) {
        int sh = __shfl_sync(0xffffffffu, s, h2);
        float wv = __shfl_sync(0xffffffffu, e, h2) / Z;
        const float4* row = (const float4*)(g_so + ((size_t)bh * HT + sh) * DH);
        float4 t = row[lane];
        acc.x = fmaf(wv, t.x, acc.x);
        acc.y = fmaf(wv, t.y, acc.y);
        acc.z = fmaf(wv, t.z, acc.z);
        acc.w = fmaf(wv, t.w, acc.w);
    }
    float* dst = g_attn + ((size_t)(b * T_LEN + pos)) * EMB + hh * DH;
    ((float4*)dst)[lane] = acc;
}

// ----------------------------- launcher -------------------------------------
extern "C" void kernel_launch(void* const* d_in, const int* in_sizes, int n_in,
                              void* d_out, int out_size)
{
    const float* x = (const float*)d_in[0];
    const unsigned char* pm = (const unsigned char*)d_in[1];
    const float* rot = (const float*)d_in[2];
    const float* Wqk = (const float*)d_in[3];
    const float* Wv = (const float*)d_in[4];
    const float* Wout = (const float*)d_in[5];
    const float* bout = (const float*)d_in[6];
    float* out = (float*)d_out;

    float *qk, *v, *rv, *attn;
    cudaGetSymbolAddress((void**)&qk, g_qk);
    cudaGetSymbolAddress((void**)&v, g_v);
    cudaGetSymbolAddress((void**)&rv, g_rv);
    cudaGetSymbolAddress((void**)&attn, g_attn);

    dim3 gproj(EMB / BN, BT / BM, 1);
    gemm_kernel<<<gproj, 256>>>(x, Wqk, qk, nullptr, BT, EMB, EMB, EMB, EMB, EMB, 0, 0, 1, 0);
    gemm_kernel<<<gproj, 256>>>(x, Wv, v, nullptr, BT, EMB, EMB, EMB, EMB, EMB, 0, 0, 1, 0);

    // rv[bh] = qk_head[bh] (8192x128) @ rot (128x512)
    dim3 ghash(512 / BN, T_LEN / BM, BHD);
    gemm_kernel<<<ghash, 256>>>(qk, rot, rv, nullptr, T_LEN, 512, DH, EMB, 512, 512,
                                (long long)T_LEN * EMB, DH, N_HASH, (long long)T_LEN * 512);

    bucket_kernel<<<(BHD * HT) / 256, 256>>>();
    zero_counts_kernel<<<(BHD * NBTOT + 255) / 256, 256>>>();
    hist_kernel<<<(BHD * HT) / 256, 256>>>();
    scan_kernel<<<BHD, NBTOT>>>();
    scatter_kernel<<<(BHD * N_HASH * NB) / 8, 256>>>();

    cudaFuncSetAttribute(attn_kernel, cudaFuncAttributeMaxDynamicSharedMemorySize, SMEM_ATT);
    attn_kernel<<<dim3(NCHUNK, BHD), 256, SMEM_ATT>>>(pm);

    combine_kernel<<<(BHD * T_LEN) / 8, 256>>>();

    gemm_kernel<<<gproj, 256>>>(attn, Wout, out, bout, BT, EMB, EMB, EMB, EMB, EMB, 0, 0, 1, 0);
}

// round 4
// speedup vs baseline: 1.2231x; 1.2231x over previous
#include <cuda_runtime.h>
#include <cuda_bf16.h>
#include <cstdint>
#include <math.h>

#define T_LEN   8192
#define B_SZ    2
#define N_HEADS 8
#define DH      128
#define EMB     1024
#define BHD     16          // B * HEADS
#define N_HASH  8
#define NB      128         // buckets per hash
#define NBTOT   1024        // N_HASH * NB
#define BUCKETSZ 64
#define NCHUNK  1024        // per bh
#define HT      65536       // N_HASH * T
#define BT      16384       // B * T
#define QSCALE  0.08838834764831843f

// ----------------------------- scratch (static device memory; no allocs) ---
__device__ float g_qk[(size_t)BT * EMB];            // fp32 (exact path + attention)
__device__ float g_v[(size_t)BT * EMB];
__device__ __nv_bfloat16 g_x_hi[(size_t)BT * EMB];
__device__ __nv_bfloat16 g_x_lo[(size_t)BT * EMB];
__device__ __nv_bfloat16 g_attn_hi[(size_t)BT * EMB];
__device__ __nv_bfloat16 g_attn_lo[(size_t)BT * EMB];
__device__ __nv_bfloat16 g_wvT_hi[EMB * EMB];
__device__ __nv_bfloat16 g_wvT_lo[EMB * EMB];
__device__ __nv_bfloat16 g_woutT_hi[EMB * EMB];
__device__ __nv_bfloat16 g_woutT_lo[EMB * EMB];
__device__ float g_rv[(size_t)BHD * T_LEN * 512];
__device__ int   g_buckets[(size_t)BHD * HT];
__device__ int   g_counts[BHD * NBTOT];
__device__ int   g_offsets[BHD * NBTOT];
__device__ int   g_st[(size_t)BHD * HT];
__device__ int   g_undo[(size_t)BHD * HT];
__device__ float g_so[(size_t)BHD * HT * DH];
__device__ float g_slog[(size_t)BHD * HT];

// ----------------------------- exact fp32 GEMM (sequential-k; bucket path) --
#define BM 64
#define BN 64
#define BKK 16

__global__ void gemm_kernel(const float* __restrict__ A, const float* __restrict__ Bm,
                            float* __restrict__ C, const float* __restrict__ bias,
                            int M, int N, int K, int lda, int ldb, int ldc,
                            long long sAouter, long long sAinner, int innerDiv,
                            long long sC)
{
    __shared__ float As[BKK][BM + 1];
    __shared__ float Bs[BKK][BN];
    int z = blockIdx.z;
    const float* Ab = A + (long long)(z / innerDiv) * sAouter + (long long)(z % innerDiv) * sAinner;
    float* Cb = C + (long long)z * sC;
    int row0 = blockIdx.y * BM;
    int col0 = blockIdx.x * BN;
    int tid = threadIdx.x;
    int tx = tid & 15, ty = tid >> 4;
    float acc[4][4];
#pragma unroll
    for (int i = 0; i < 4; i++)
#pragma unroll
        for (int j = 0; j < 4; j++) acc[i][j] = 0.f;

    for (int k0 = 0; k0 < K; k0 += BKK) {
#pragma unroll
        for (int i = 0; i < 4; i++) {
            int e = tid + 256 * i;
            int r = e >> 4, kk = e & 15;
            As[kk][r] = __ldg(&Ab[(size_t)(row0 + r) * lda + k0 + kk]);
        }
#pragma unroll
        for (int i = 0; i < 4; i++) {
            int e = tid + 256 * i;
            int kk = e >> 6, c = e & 63;
            Bs[kk][c] = __ldg(&Bm[(size_t)(k0 + kk) * ldb + col0 + c]);
        }
        __syncthreads();
#pragma unroll
        for (int kk = 0; kk < BKK; kk++) {
            float a[4], bb[4];
#pragma unroll
            for (int i = 0; i < 4; i++) a[i] = As[kk][ty * 4 + i];
#pragma unroll
            for (int i = 0; i < 4; i++) bb[i] = Bs[kk][tx * 4 + i];
#pragma unroll
            for (int i = 0; i < 4; i++)
#pragma unroll
                for (int j = 0; j < 4; j++) acc[i][j] = fmaf(a[i], bb[j], acc[i][j]);
        }
        __syncthreads();
    }
#pragma unroll
    for (int i = 0; i < 4; i++) {
        int r = row0 + ty * 4 + i;
#pragma unroll
        for (int j = 0; j < 4; j++) {
            int c = col0 + tx * 4 + j;
            float o = acc[i][j];
            if (bias) o += bias[c];
            Cb[(size_t)r * ldc + c] = o;
        }
    }
}

// ----------------------------- mma helpers (portable PTX, sm_80+) ----------
__device__ __forceinline__ uint32_t smem_u32(const void* p) {
    uint32_t a;
    asm("{ .reg .u64 t; cvta.to.shared.u64 t, %1; cvt.u32.u64 %0, t; }" : "=r"(a) : "l"(p));
    return a;
}
__device__ __forceinline__ void ldm_x4(uint32_t* r, uint32_t addr) {
    asm volatile("ldmatrix.sync.aligned.m8n8.x4.shared.b16 {%0,%1,%2,%3}, [%4];"
        : "=r"(r[0]), "=r"(r[1]), "=r"(r[2]), "=r"(r[3]) : "r"(addr));
}
__device__ __forceinline__ void ldm_x2(uint32_t* r, uint32_t addr) {
    asm volatile("ldmatrix.sync.aligned.m8n8.x2.shared.b16 {%0,%1}, [%2];"
        : "=r"(r[0]), "=r"(r[1]) : "r"(addr));
}
__device__ __forceinline__ void mma16816(float* d, const uint32_t* a, const uint32_t* b) {
    asm volatile("mma.sync.aligned.m16n8k16.row.col.f32.bf16.bf16.f32 "
        "{%0,%1,%2,%3}, {%4,%5,%6,%7}, {%8,%9}, {%0,%1,%2,%3};"
        : "+f"(d[0]), "+f"(d[1]), "+f"(d[2]), "+f"(d[3])
        : "r"(a[0]), "r"(a[1]), "r"(a[2]), "r"(a[3]), "r"(b[0]), "r"(b[1]));
}

// ----------------------------- bf16-split tensor-core GEMM (smooth path) ----
// C[M,N] = A[M,K] @ B^T  (B stored [N][K], K-major); A,B as bf16 (hi,lo) pairs.
// Block tile 128x128, BK=64, 8 warps (2m x 4n), warp tile 64x32.
#define SA_HI 0
#define SA_LO 16384
#define SB_HI 32768
#define SB_LO 49152
#define GEMM_SMEM 65536

__global__ void __launch_bounds__(256) mma_gemm(
    const __nv_bfloat16* __restrict__ Ahi, const __nv_bfloat16* __restrict__ Alo,
    const __nv_bfloat16* __restrict__ Bhi, const __nv_bfloat16* __restrict__ Blo,
    float* __restrict__ C, const float* __restrict__ bias,
    int K, int lda, int ldb, int ldc)
{
    extern __shared__ char sm[];
    uint32_t sb = smem_u32(sm);
    int tid = threadIdx.x, lane = tid & 31, wid = tid >> 5;
    int wm = wid & 1, wn = wid >> 1;

    int m0 = blockIdx.y * 128, n0 = blockIdx.x * 128;

    float acc[4][4][4];
#pragma unroll
    for (int mt = 0; mt < 4; mt++)
#pragma unroll
        for (int nt = 0; nt < 4; nt++)
#pragma unroll
            for (int i = 0; i < 4; i++) acc[mt][nt][i] = 0.f;

    int nch = K >> 6;
    for (int ch = 0; ch < nch; ch++) {
        int k0 = ch << 6;
        const __nv_bfloat16* Abh = Ahi + (size_t)m0 * lda + k0;
        const __nv_bfloat16* Abl = Alo + (size_t)m0 * lda + k0;
        const __nv_bfloat16* Bbh = Bhi + (size_t)n0 * ldb + k0;
        const __nv_bfloat16* Bbl = Blo + (size_t)n0 * ldb + k0;
#pragma unroll
        for (int i = 0; i < 4; i++) {
            int idx = tid + (i << 8);            // 1024 chunks of 16B per tile
            int row = idx >> 3, seg = idx & 7;
            uint32_t off = (uint32_t)((row << 7) + (seg << 4));
            uint32_t sw = off ^ ((off >> 3) & 0x70);
            *(uint4*)(sm + SA_HI + sw) = *(const uint4*)(Abh + (size_t)row * lda + (seg << 3));
            *(uint4*)(sm + SA_LO + sw) = *(const uint4*)(Abl + (size_t)row * lda + (seg << 3));
            *(uint4*)(sm + SB_HI + sw) = *(const uint4*)(Bbh + (size_t)row * ldb + (seg << 3));
            *(uint4*)(sm + SB_LO + sw) = *(const uint4*)(Bbl + (size_t)row * ldb + (seg << 3));
        }
        __syncthreads();
#pragma unroll
        for (int kk = 0; kk < 4; kk++) {
            uint32_t afh[4][4], afl[4][4];
#pragma unroll
            for (int mt = 0; mt < 4; mt++) {
                int row = wm * 64 + mt * 16 + (lane & 15);
                uint32_t off = (uint32_t)((row << 7) + (kk << 5) + ((lane >> 4) << 4));
                uint32_t sw = off ^ ((off >> 3) & 0x70);
                ldm_x4(afh[mt], sb + SA_HI + sw);
                ldm_x4(afl[mt], sb + SA_LO + sw);
            }
            uint32_t bfh[4][2], bfl[4][2];
#pragma unroll
            for (int nt = 0; nt < 4; nt++) {
                int row = wn * 32 + nt * 8 + (lane & 7);
                uint32_t off = (uint32_t)((row << 7) + (kk << 5) + (((lane >> 3) & 1) << 4));
                uint32_t sw = off ^ ((off >> 3) & 0x70);
                ldm_x2(bfh[nt], sb + SB_HI + sw);
                ldm_x2(bfl[nt], sb + SB_LO + sw);
            }
#pragma unroll
            for (int mt = 0; mt < 4; mt++)
#pragma unroll
                for (int nt = 0; nt < 4; nt++) {
                    mma16816(acc[mt][nt], afh[mt], bfh[nt]);
                    mma16816(acc[mt][nt], afh[mt], bfl[nt]);
                    mma16816(acc[mt][nt], afl[mt], bfh[nt]);
                }
        }
        __syncthreads();
    }

#pragma unroll
    for (int mt = 0; mt < 4; mt++) {
#pragma unroll
        for (int nt = 0; nt < 4; nt++) {
            int c = n0 + wn * 32 + nt * 8 + ((lane & 3) << 1);
#pragma unroll
            for (int half = 0; half < 2; half++) {
                int r = m0 + wm * 64 + mt * 16 + (lane >> 2) + half * 8;
                float v0 = acc[mt][nt][half * 2 + 0];
                float v1 = acc[mt][nt][half * 2 + 1];
                if (bias) { v0 += bias[c]; v1 += bias[c + 1]; }
                *(float2*)(C + (size_t)r * ldc + c) = make_float2(v0, v1);
            }
        }
    }
}

// ----------------------------- conversions ----------------------------------
__global__ void convert_pair_kernel(const float* __restrict__ src,
                                    __nv_bfloat16* __restrict__ hi,
                                    __nv_bfloat16* __restrict__ lo, int n)
{
    int i = blockIdx.x * 256 + threadIdx.x;
    if (i < n) {
        float v = src[i];
        __nv_bfloat16 h = __float2bfloat16_rn(v);
        hi[i] = h;
        lo[i] = __float2bfloat16_rn(v - __bfloat162float(h));
    }
}

// transpose R x C fp32 -> C x R bf16 pair
__global__ void transpose_pair_kernel(const float* __restrict__ src,
                                      __nv_bfloat16* __restrict__ dhi,
                                      __nv_bfloat16* __restrict__ dlo, int R, int C)
{
    __shared__ float t[32][33];
    int c0 = blockIdx.x * 32, r0 = blockIdx.y * 32;
    int x = threadIdx.x, y = threadIdx.y;
    for (int i = 0; i < 32; i += 8)
        t[y + i][x] = src[(size_t)(r0 + y + i) * C + c0 + x];
    __syncthreads();
    for (int i = 0; i < 32; i += 8) {
        float v = t[x][y + i];
        __nv_bfloat16 h = __float2bfloat16_rn(v);
        size_t o = (size_t)(c0 + y + i) * R + r0 + x;
        dhi[o] = h;
        dlo[o] = __float2bfloat16_rn(v - __bfloat162float(h));
    }
}

// ----------------------------- bucket argmax (coalesced) --------------------
__global__ void bucket_kernel()
{
    int idx = blockIdx.x * 256 + threadIdx.x;           // BHD*T*8 threads
    int h = idx & 7;
    int t = (idx >> 3) & (T_LEN - 1);
    int bh = idx >> 16;
    const float4* p = (const float4*)(g_rv + ((size_t)bh * T_LEN + t) * 512 + h * 64);
    float maxv = -1e30f, minv = 1e30f;
    int imax = 0, imin = 0;
#pragma unroll
    for (int i = 0; i < 16; i++) {
        float4 q = p[i];
        float vv[4] = {q.x, q.y, q.z, q.w};
#pragma unroll
        for (int c = 0; c < 4; c++) {
            int j = i * 4 + c;
            if (vv[c] > maxv) { maxv = vv[c]; imax = j; }
            if (vv[c] < minv) { minv = vv[c]; imin = j; }
        }
    }
    int bi = (maxv >= -minv) ? imax : 64 + imin;
    g_buckets[(size_t)bh * HT + (size_t)h * T_LEN + t] = bi + h * NB;
}

__global__ void zero_counts_kernel()
{
    int idx = blockIdx.x * 256 + threadIdx.x;
    if (idx < BHD * NBTOT) g_counts[idx] = 0;
}

__global__ void hist_kernel()
{
    int idx = blockIdx.x * 256 + threadIdx.x;
    int bh = idx >> 16;
    atomicAdd(&g_counts[bh * NBTOT + g_buckets[idx]], 1);
}

__global__ void scan_kernel()
{
    __shared__ int s[NBTOT];
    int bh = blockIdx.x, t = threadIdx.x;
    int my = g_counts[bh * NBTOT + t];
    s[t] = my;
    __syncthreads();
    for (int d = 1; d < NBTOT; d <<= 1) {
        int v = (t >= d) ? s[t - d] : 0;
        __syncthreads();
        s[t] += v;
        __syncthreads();
    }
    g_offsets[bh * NBTOT + t] = s[t] - my;
}

// single-pass stable rank: one warp per (bh, hash)
__global__ void scatter_kernel()
{
    __shared__ int cnt[4][NB];
    int w = threadIdx.x >> 5, lane = threadIdx.x & 31;
    int wg = blockIdx.x * 4 + w;                        // 0..BHD*N_HASH-1
    int bh = wg >> 3, h = wg & 7;
#pragma unroll
    for (int i = 0; i < 4; i++)
        cnt[w][lane * 4 + i] = g_offsets[bh * NBTOT + h * NB + lane * 4 + i];
    __syncwarp();
    const int* bk = g_buckets + (size_t)bh * HT + (size_t)h * T_LEN;
    int* stp = g_st + (size_t)bh * HT;
    int* unp = g_undo + (size_t)bh * HT + (size_t)h * T_LEN;
    for (int t0 = 0; t0 < T_LEN; t0 += 32) {
        int t = t0 + lane;
        int b = bk[t] - h * NB;
        unsigned mask = __match_any_sync(0xffffffffu, b);
        int lead = __ffs(mask) - 1;
        int pre = __popc(mask & ((1u << lane) - 1u));
        int base = 0;
        if (lane == lead) base = cnt[w][b];
        base = __shfl_sync(0xffffffffu, base, lead);
        int rnk = base + pre;
        if (lane == lead) cnt[w][b] = base + __popc(mask);
        stp[rnk] = t;
        unp[t] = rnk;
        __syncwarp();
    }
}

// ----------------------------- chunked attention ----------------------------
#define SMEM_ATT ((8320 + 16512 + 16512 + 8256 + 256) * 4 + 256 * 4)

__global__ void attn_kernel(const unsigned char* __restrict__ pm)
{
    extern __shared__ float smem[];
    float* qT  = smem;                       // pitch 65
    float* ks  = qT + 8320;                  // pitch 129
    float* vs  = ks + 16512;                 // pitch 129
    float* scb = vs + 16512;                 // [j][r] pitch 64, later [r][d] pitch 129
    float* red = scb + 8256;                 // 4 x 64
    int* posk = (int*)(red + 256);
    int* padk = posk + 128;

    int bh = blockIdx.y, c = blockIdx.x;
    int b = bh >> 3, h = bh & 7;
    int tid = threadIdx.x, lane = tid & 31, w = tid >> 5;

    if (tid < 128) {
        int j = tid;
        int cprev = (c == 0) ? (NCHUNK - 1) : (c - 1);
        int slot = (j < BUCKETSZ) ? c * BUCKETSZ + j : cprev * BUCKETSZ + (j - BUCKETSZ);
        int pos = g_st[(size_t)bh * HT + slot];
        posk[j] = pos;
        padk[j] = pm[b * T_LEN + pos] ? 1 : 0;
    }
    __syncthreads();

    for (int rr = 0; rr < 8; rr++) {
        int r = w * 8 + rr;
        int pos = posk[r];
        const float* src = g_qk + ((size_t)(b * T_LEN + pos)) * EMB + h * DH;
#pragma unroll
        for (int kk = 0; kk < 4; kk++) {
            int f = lane + 32 * kk;
            qT[f * 65 + r] = src[f] * QSCALE;
        }
    }
    for (int jj = 0; jj < 16; jj++) {
        int j = w * 16 + jj;
        int pos = posk[j];
        const float* src = g_qk + ((size_t)(b * T_LEN + pos)) * EMB + h * DH;
        float v0[4]; float ss = 0.f;
#pragma unroll
        for (int kk = 0; kk < 4; kk++) { v0[kk] = src[lane + 32 * kk]; ss += v0[kk] * v0[kk]; }
#pragma unroll
        for (int o = 16; o > 0; o >>= 1) ss += __shfl_xor_sync(0xffffffffu, ss, o);
        float rn = rsqrtf(fmaxf(ss, 1e-12f));
#pragma unroll
        for (int kk = 0; kk < 4; kk++) ks[j * 129 + lane + 32 * kk] = v0[kk] * rn;
        const float* sv = g_v + ((size_t)(b * T_LEN + pos)) * EMB + h * DH;
#pragma unroll
        for (int kk = 0; kk < 4; kk++) vs[j * 129 + lane + 32 * kk] = sv[lane + 32 * kk];
    }
    __syncthreads();

    int rsub = tid & 15;
    int j0 = (tid >> 4) * 8;
    {
        float acc[4][8];
#pragma unroll
        for (int i = 0; i < 4; i++)
#pragma unroll
            for (int j = 0; j < 8; j++) acc[i][j] = 0.f;
#pragma unroll 4
        for (int f = 0; f < 128; f++) {
            float qv[4];
#pragma unroll
            for (int ri = 0; ri < 4; ri++) qv[ri] = qT[f * 65 + rsub + 16 * ri];
#pragma unroll
            for (int ji = 0; ji < 8; ji++) {
                float kv = ks[(j0 + ji) * 129 + f];
#pragma unroll
                for (int ri = 0; ri < 4; ri++) acc[ri][ji] = fmaf(qv[ri], kv, acc[ri][ji]);
            }
        }
#pragma unroll
        for (int ri = 0; ri < 4; ri++) {
            int r = rsub + 16 * ri;
            int pq = posk[r];
#pragma unroll
            for (int ji = 0; ji < 8; ji++) {
                int j = j0 + ji;
                float s = acc[ri][ji];
                if (pq == posk[j]) s = -1e5f;
                else if (padk[j]) s = -1e9f;
                scb[j * 64 + r] = s;
            }
        }
    }
    __syncthreads();

    {
        int r = tid & 63, q4 = tid >> 6;
        float m = -1e30f;
        for (int jj = 0; jj < 32; jj++) m = fmaxf(m, scb[(q4 * 32 + jj) * 64 + r]);
        red[q4 * 64 + r] = m;
        __syncthreads();
        float M = fmaxf(fmaxf(red[r], red[64 + r]), fmaxf(red[128 + r], red[192 + r]));
        float ssum = 0.f;
        for (int jj = 0; jj < 32; jj++) ssum += expf(scb[(q4 * 32 + jj) * 64 + r] - M);
        __syncthreads();
        red[q4 * 64 + r] = ssum;
        __syncthreads();
        float Z = red[r] + red[64 + r] + red[128 + r] + red[192 + r];
        float lse = M + logf(Z);
        if (q4 == 0) g_slog[(size_t)bh * HT + c * BUCKETSZ + r] = lse;
        for (int jj = 0; jj < 32; jj++) {
            int j = q4 * 32 + jj;
            scb[j * 64 + r] = expf(scb[j * 64 + r] - lse);
        }
    }
    __syncthreads();

    {
        int d0 = (tid >> 4) * 8;
        float a2[4][8];
#pragma unroll
        for (int i = 0; i < 4; i++)
#pragma unroll
            for (int j = 0; j < 8; j++) a2[i][j] = 0.f;
#pragma unroll 4
        for (int kv = 0; kv < 128; kv++) {
            float pv[4];
#pragma unroll
            for (int ri = 0; ri < 4; ri++) pv[ri] = scb[kv * 64 + rsub + 16 * ri];
#pragma unroll
            for (int di = 0; di < 8; di++) {
                float vv = vs[kv * 129 + d0 + di];
#pragma unroll
                for (int ri = 0; ri < 4; ri++) a2[ri][di] = fmaf(pv[ri], vv, a2[ri][di]);
            }
        }
        __syncthreads();
#pragma unroll
        for (int ri = 0; ri < 4; ri++) {
            int r = rsub + 16 * ri;
#pragma unroll
            for (int di = 0; di < 8; di++) scb[r * 129 + d0 + di] = a2[ri][di];
        }
    }
    __syncthreads();

    for (int rr = 0; rr < 8; rr++) {
        int r = w * 8 + rr;
        float* dst = g_so + ((size_t)bh * HT + c * BUCKETSZ + r) * DH;
#pragma unroll
        for (int kk = 0; kk < 4; kk++) {
            int d = lane + 32 * kk;
            dst[d] = scb[r * 129 + d];
        }
    }
}

// ----------------------------- combine hash rounds --------------------------
__global__ void combine_kernel()
{
    int gw = (blockIdx.x * 256 + threadIdx.x) >> 5;    // 0..BHD*T-1
    int lane = threadIdx.x & 31;
    int bh = gw >> 13;
    int pos = gw & (T_LEN - 1);
    int b = bh >> 3, hh = bh & 7;

    int s = 0;
    float l = -1e30f;
    if (lane < N_HASH) {
        s = g_undo[(size_t)bh * HT + (size_t)lane * T_LEN + pos];
        l = g_slog[(size_t)bh * HT + s];
    }
    float m = l;
#pragma unroll
    for (int o = 16; o > 0; o >>= 1) m = fmaxf(m, __shfl_xor_sync(0xffffffffu, m, o));
    float e = (lane < N_HASH) ? expf(l - m) : 0.f;
    float Z = e;
#pragma unroll
    for (int o = 16; o > 0; o >>= 1) Z += __shfl_xor_sync(0xffffffffu, Z, o);

    float4 acc = make_float4(0.f, 0.f, 0.f, 0.f);
#pragma unroll
    for (int h2 = 0; h2 < N_HASH; h2++) {
        int sh = __shfl_sync(0xffffffffu, s, h2);
        float wv = __shfl_sync(0xffffffffu, e, h2) / Z;
        const float4* row = (const float4*)(g_so + ((size_t)bh * HT + sh) * DH);
        float4 t = row[lane];
        acc.x = fmaf(wv, t.x, acc.x);
        acc.y = fmaf(wv, t.y, acc.y);
        acc.z = fmaf(wv, t.z, acc.z);
        acc.w = fmaf(wv, t.w, acc.w);
    }
    size_t off = ((size_t)(b * T_LEN + pos)) * EMB + hh * DH + lane * 4;
    float fv[4] = {acc.x, acc.y, acc.z, acc.w};
    __nv_bfloat16 hi[4]; float lo[4];
#pragma unroll
    for (int u = 0; u < 4; u++) { hi[u] = __float2bfloat16_rn(fv[u]); lo[u] = fv[u] - __bfloat162float(hi[u]); }
    ((__nv_bfloat162*)(g_attn_hi + off))[0] = __nv_bfloat162(hi[0], hi[1]);
    ((__nv_bfloat162*)(g_attn_hi + off))[1] = __nv_bfloat162(hi[2], hi[3]);
    ((__nv_bfloat162*)(g_attn_lo + off))[0] = __floats2bfloat162_rn(lo[0], lo[1]);
    ((__nv_bfloat162*)(g_attn_lo + off))[1] = __floats2bfloat162_rn(lo[2], lo[3]);
}

// ----------------------------- launcher -------------------------------------
extern "C" void kernel_launch(void* const* d_in, const int* in_sizes, int n_in,
                              void* d_out, int out_size)
{
    const float* x = (const float*)d_in[0];
    const unsigned char* pm = (const unsigned char*)d_in[1];
    const float* rot = (const float*)d_in[2];
    const float* Wqk = (const float*)d_in[3];
    const float* Wv = (const float*)d_in[4];
    const float* Wout = (const float*)d_in[5];
    const float* bout = (const float*)d_in[6];
    float* out = (float*)d_out;

    float *qk, *v, *rv;
    __nv_bfloat16 *xhi, *xlo, *athi, *atlo;
    __nv_bfloat16 *wvh, *wvl, *woh, *wol;
    cudaGetSymbolAddress((void**)&qk, g_qk);
    cudaGetSymbolAddress((void**)&v, g_v);
    cudaGetSymbolAddress((void**)&rv, g_rv);
    cudaGetSymbolAddress((void**)&xhi, g_x_hi);
    cudaGetSymbolAddress((void**)&xlo, g_x_lo);
    cudaGetSymbolAddress((void**)&athi, g_attn_hi);
    cudaGetSymbolAddress((void**)&atlo, g_attn_lo);
    cudaGetSymbolAddress((void**)&wvh, g_wvT_hi);
    cudaGetSymbolAddress((void**)&wvl, g_wvT_lo);
    cudaGetSymbolAddress((void**)&woh, g_woutT_hi);
    cudaGetSymbolAddress((void**)&wol, g_woutT_lo);

    cudaFuncSetAttribute(mma_gemm, cudaFuncAttributeMaxDynamicSharedMemorySize, GEMM_SMEM);
    cudaFuncSetAttribute(attn_kernel, cudaFuncAttributeMaxDynamicSharedMemorySize, SMEM_ATT);

    // conversions for tensor-core (smooth) GEMMs
    convert_pair_kernel<<<(BT * EMB) / 256, 256>>>(x, xhi, xlo, BT * EMB);
    transpose_pair_kernel<<<dim3(EMB / 32, EMB / 32), dim3(32, 8)>>>(Wv, wvh, wvl, EMB, EMB);
    transpose_pair_kernel<<<dim3(EMB / 32, EMB / 32), dim3(32, 8)>>>(Wout, woh, wol, EMB, EMB);

    // qk = x @ Wqk  — EXACT fp32 sequential-k (bucket decisions depend on it)
    gemm_kernel<<<dim3(EMB / BN, BT / BM, 1), 256>>>(x, Wqk, qk, nullptr,
        BT, EMB, EMB, EMB, EMB, EMB, 0, 0, 1, 0);
    // v = x @ Wv  — tensor cores (smooth path)
    mma_gemm<<<dim3(EMB / 128, BT / 128, 1), 256, GEMM_SMEM>>>(
        xhi, xlo, wvh, wvl, v, nullptr, EMB, EMB, EMB, EMB);
    // rv[bh] = qk_head[bh] (8192x128) @ rot (128x512) — EXACT fp32
    gemm_kernel<<<dim3(512 / BN, T_LEN / BM, BHD), 256>>>(qk, rot, rv, nullptr,
        T_LEN, 512, DH, EMB, 512, 512,
        (long long)T_LEN * EMB, DH, N_HASH, (long long)T_LEN * 512);

    bucket_kernel<<<(BHD * HT) / 256, 256>>>();
    zero_counts_kernel<<<(BHD * NBTOT + 255) / 256, 256>>>();
    hist_kernel<<<(BHD * HT) / 256, 256>>>();
    scan_kernel<<<BHD, NBTOT>>>();
    scatter_kernel<<<(BHD * N_HASH) / 4, 128>>>();

    attn_kernel<<<dim3(NCHUNK, BHD), 256, SMEM_ATT>>>(pm);

    combine_kernel<<<(BHD * T_LEN) / 8, 256>>>();

    // out = attn @ Wout + bout — tensor cores (smooth path)
    mma_gemm<<<dim3(EMB / 128, BT / 128, 1), 256, GEMM_SMEM>>>(
        athi, atlo, woh, wol, out, bout, EMB, EMB, EMB, EMB);
}

// round 5
// speedup vs baseline: 1.7101x; 1.3981x over previous
#include <cuda_runtime.h>
#include <cuda_bf16.h>
#include <cstdint>
#include <math.h>

#define T_LEN   8192
#define B_SZ    2
#define N_HEADS 8
#define DH      128
#define EMB     1024
#define BHD     16          // B * HEADS
#define N_HASH  8
#define NB      128         // buckets per hash
#define NBTOT   1024        // N_HASH * NB
#define BUCKETSZ 64
#define NCHUNK  1024        // per bh
#define HT      65536       // N_HASH * T
#define BT      16384       // B * T
#define QSCALE  0.08838834764831843f

// ----------------------------- scratch (static device memory; no allocs) ---
__device__ float g_qk[(size_t)BT * EMB];            // fp32 (exact path + attention)
__device__ float g_v[(size_t)BT * EMB];
__device__ __nv_bfloat16 g_x_hi[(size_t)BT * EMB];
__device__ __nv_bfloat16 g_x_lo[(size_t)BT * EMB];
__device__ __nv_bfloat16 g_attn_hi[(size_t)BT * EMB];
__device__ __nv_bfloat16 g_attn_lo[(size_t)BT * EMB];
__device__ __nv_bfloat16 g_wvT_hi[EMB * EMB];
__device__ __nv_bfloat16 g_wvT_lo[EMB * EMB];
__device__ __nv_bfloat16 g_woutT_hi[EMB * EMB];
__device__ __nv_bfloat16 g_woutT_lo[EMB * EMB];
__device__ float g_rv[(size_t)BHD * T_LEN * 512];
__device__ int   g_buckets[(size_t)BHD * HT];
__device__ int   g_counts[BHD * NBTOT];
__device__ int   g_offsets[BHD * NBTOT];
__device__ int   g_st[(size_t)BHD * HT];
__device__ int   g_undo[(size_t)BHD * HT];
__device__ float g_so[(size_t)BHD * HT * DH];
__device__ float g_slog[(size_t)BHD * HT];

// ----------------------------- exact fp32 GEMM (sequential-k; bucket path) --
// 128x128 tile, 256 threads, 8x8 per thread. Per-output k accumulation is a
// single accumulator in strictly ascending k order -> bitwise identical to the
// round-1/round-4 passing kernel regardless of tiling.
#define GBM 128
#define GBN 128
#define GBK 16

__global__ void __launch_bounds__(256, 2) gemm_kernel(
    const float* __restrict__ A, const float* __restrict__ Bm,
    float* __restrict__ C, const float* __restrict__ bias,
    int M, int N, int K, int lda, int ldb, int ldc,
    long long sAouter, long long sAinner, int innerDiv,
    long long sC)
{
    __shared__ float As[GBK][GBM + 4];   // [kk][row]
    __shared__ float Bs[GBK][GBN];       // [kk][col]
    int z = blockIdx.z;
    const float* Ab = A + (long long)(z / innerDiv) * sAouter + (long long)(z % innerDiv) * sAinner;
    float* Cb = C + (long long)z * sC;
    int row0 = blockIdx.y * GBM;
    int col0 = blockIdx.x * GBN;
    int tid = threadIdx.x;
    int tx = tid & 15, ty = tid >> 4;

    float acc[8][8];
#pragma unroll
    for (int i = 0; i < 8; i++)
#pragma unroll
        for (int j = 0; j < 8; j++) acc[i][j] = 0.f;

    for (int k0 = 0; k0 < K; k0 += GBK) {
#pragma unroll
        for (int i = 0; i < 2; i++) {
            int idx = tid + (i << 8);          // 0..511
            int row = idx >> 2, ks4 = (idx & 3) << 2;
            float4 a = *(const float4*)&Ab[(size_t)(row0 + row) * lda + k0 + ks4];
            As[ks4 + 0][row] = a.x;
            As[ks4 + 1][row] = a.y;
            As[ks4 + 2][row] = a.z;
            As[ks4 + 3][row] = a.w;
        }
#pragma unroll
        for (int i = 0; i < 2; i++) {
            int idx = tid + (i << 8);
            int kk = idx >> 5, c4 = (idx & 31) << 2;
            *(float4*)&Bs[kk][c4] = *(const float4*)&Bm[(size_t)(k0 + kk) * ldb + col0 + c4];
        }
        __syncthreads();
#pragma unroll
        for (int kk = 0; kk < GBK; kk++) {
            float4 a0 = *(float4*)&As[kk][ty * 4];
            float4 a1 = *(float4*)&As[kk][64 + ty * 4];
            float4 b0 = *(float4*)&Bs[kk][tx * 4];
            float4 b1 = *(float4*)&Bs[kk][64 + tx * 4];
            float av[8] = {a0.x, a0.y, a0.z, a0.w, a1.x, a1.y, a1.z, a1.w};
            float bv[8] = {b0.x, b0.y, b0.z, b0.w, b1.x, b1.y, b1.z, b1.w};
#pragma unroll
            for (int i = 0; i < 8; i++)
#pragma unroll
                for (int j = 0; j < 8; j++) acc[i][j] = fmaf(av[i], bv[j], acc[i][j]);
        }
        __syncthreads();
    }
#pragma unroll
    for (int ih = 0; ih < 2; ih++)
#pragma unroll
        for (int i = 0; i < 4; i++) {
            int r = row0 + ih * 64 + ty * 4 + i;
#pragma unroll
            for (int jh = 0; jh < 2; jh++) {
                int c = col0 + jh * 64 + tx * 4;
                float4 o;
                o.x = acc[ih * 4 + i][jh * 4 + 0];
                o.y = acc[ih * 4 + i][jh * 4 + 1];
                o.z = acc[ih * 4 + i][jh * 4 + 2];
                o.w = acc[ih * 4 + i][jh * 4 + 3];
                if (bias) { o.x += bias[c]; o.y += bias[c + 1]; o.z += bias[c + 2]; o.w += bias[c + 3]; }
                *(float4*)&Cb[(size_t)r * ldc + c] = o;
            }
        }
}

// ----------------------------- mma helpers (portable PTX, sm_80+) ----------
__device__ __forceinline__ uint32_t smem_u32(const void* p) {
    uint32_t a;
    asm("{ .reg .u64 t; cvta.to.shared.u64 t, %1; cvt.u32.u64 %0, t; }" : "=r"(a) : "l"(p));
    return a;
}
__device__ __forceinline__ void ldm_x4(uint32_t* r, uint32_t addr) {
    asm volatile("ldmatrix.sync.aligned.m8n8.x4.shared.b16 {%0,%1,%2,%3}, [%4];"
        : "=r"(r[0]), "=r"(r[1]), "=r"(r[2]), "=r"(r[3]) : "r"(addr));
}
__device__ __forceinline__ void ldm_x4_t(uint32_t* r, uint32_t addr) {
    asm volatile("ldmatrix.sync.aligned.m8n8.x4.trans.shared.b16 {%0,%1,%2,%3}, [%4];"
        : "=r"(r[0]), "=r"(r[1]), "=r"(r[2]), "=r"(r[3]) : "r"(addr));
}
__device__ __forceinline__ void ldm_x2(uint32_t* r, uint32_t addr) {
    asm volatile("ldmatrix.sync.aligned.m8n8.x2.shared.b16 {%0,%1}, [%2];"
        : "=r"(r[0]), "=r"(r[1]) : "r"(addr));
}
__device__ __forceinline__ void mma16816(float* d, const uint32_t* a, const uint32_t* b) {
    asm volatile("mma.sync.aligned.m16n8k16.row.col.f32.bf16.bf16.f32 "
        "{%0,%1,%2,%3}, {%4,%5,%6,%7}, {%8,%9}, {%0,%1,%2,%3};"
        : "+f"(d[0]), "+f"(d[1]), "+f"(d[2]), "+f"(d[3])
        : "r"(a[0]), "r"(a[1]), "r"(a[2]), "r"(a[3]), "r"(b[0]), "r"(b[1]));
}
__device__ __forceinline__ uint32_t packbf2(float x, float y) {
    __nv_bfloat162 p(__float2bfloat16_rn(x), __float2bfloat16_rn(y));
    return *(uint32_t*)&p;
}

// ----------------------------- bf16-split tensor-core GEMM (smooth path) ----
#define SA_HI 0
#define SA_LO 16384
#define SB_HI 32768
#define SB_LO 49152
#define GEMM_SMEM 65536

__global__ void __launch_bounds__(256) mma_gemm(
    const __nv_bfloat16* __restrict__ Ahi, const __nv_bfloat16* __restrict__ Alo,
    const __nv_bfloat16* __restrict__ Bhi, const __nv_bfloat16* __restrict__ Blo,
    float* __restrict__ C, const float* __restrict__ bias,
    int K, int lda, int ldb, int ldc)
{
    extern __shared__ char sm[];
    uint32_t sb = smem_u32(sm);
    int tid = threadIdx.x, lane = tid & 31, wid = tid >> 5;
    int wm = wid & 1, wn = wid >> 1;

    int m0 = blockIdx.y * 128, n0 = blockIdx.x * 128;

    float acc[4][4][4];
#pragma unroll
    for (int mt = 0; mt < 4; mt++)
#pragma unroll
        for (int nt = 0; nt < 4; nt++)
#pragma unroll
            for (int i = 0; i < 4; i++) acc[mt][nt][i] = 0.f;

    int nch = K >> 6;
    for (int ch = 0; ch < nch; ch++) {
        int k0 = ch << 6;
        const __nv_bfloat16* Abh = Ahi + (size_t)m0 * lda + k0;
        const __nv_bfloat16* Abl = Alo + (size_t)m0 * lda + k0;
        const __nv_bfloat16* Bbh = Bhi + (size_t)n0 * ldb + k0;
        const __nv_bfloat16* Bbl = Blo + (size_t)n0 * ldb + k0;
#pragma unroll
        for (int i = 0; i < 4; i++) {
            int idx = tid + (i << 8);
            int row = idx >> 3, seg = idx & 7;
            uint32_t off = (uint32_t)((row << 7) + (seg << 4));
            uint32_t sw = off ^ ((off >> 3) & 0x70);
            *(uint4*)(sm + SA_HI + sw) = *(const uint4*)(Abh + (size_t)row * lda + (seg << 3));
            *(uint4*)(sm + SA_LO + sw) = *(const uint4*)(Abl + (size_t)row * lda + (seg << 3));
            *(uint4*)(sm + SB_HI + sw) = *(const uint4*)(Bbh + (size_t)row * ldb + (seg << 3));
            *(uint4*)(sm + SB_LO + sw) = *(const uint4*)(Bbl + (size_t)row * ldb + (seg << 3));
        }
        __syncthreads();
#pragma unroll
        for (int kk = 0; kk < 4; kk++) {
            uint32_t afh[4][4], afl[4][4];
#pragma unroll
            for (int mt = 0; mt < 4; mt++) {
                int row = wm * 64 + mt * 16 + (lane & 15);
                uint32_t off = (uint32_t)((row << 7) + (kk << 5) + ((lane >> 4) << 4));
                uint32_t sw = off ^ ((off >> 3) & 0x70);
                ldm_x4(afh[mt], sb + SA_HI + sw);
                ldm_x4(afl[mt], sb + SA_LO + sw);
            }
            uint32_t bfh[4][2], bfl[4][2];
#pragma unroll
            for (int nt = 0; nt < 4; nt++) {
                int row = wn * 32 + nt * 8 + (lane & 7);
                uint32_t off = (uint32_t)((row << 7) + (kk << 5) + (((lane >> 3) & 1) << 4));
                uint32_t sw = off ^ ((off >> 3) & 0x70);
                ldm_x2(bfh[nt], sb + SB_HI + sw);
                ldm_x2(bfl[nt], sb + SB_LO + sw);
            }
#pragma unroll
            for (int mt = 0; mt < 4; mt++)
#pragma unroll
                for (int nt = 0; nt < 4; nt++) {
                    mma16816(acc[mt][nt], afh[mt], bfh[nt]);
                    mma16816(acc[mt][nt], afh[mt], bfl[nt]);
                    mma16816(acc[mt][nt], afl[mt], bfh[nt]);
                }
        }
        __syncthreads();
    }

#pragma unroll
    for (int mt = 0; mt < 4; mt++) {
#pragma unroll
        for (int nt = 0; nt < 4; nt++) {
            int c = n0 + wn * 32 + nt * 8 + ((lane & 3) << 1);
#pragma unroll
            for (int half = 0; half < 2; half++) {
                int r = m0 + wm * 64 + mt * 16 + (lane >> 2) + half * 8;
                float v0 = acc[mt][nt][half * 2 + 0];
                float v1 = acc[mt][nt][half * 2 + 1];
                if (bias) { v0 += bias[c]; v1 += bias[c + 1]; }
                *(float2*)(C + (size_t)r * ldc + c) = make_float2(v0, v1);
            }
        }
    }
}

// ----------------------------- conversions ----------------------------------
__global__ void convert_pair_kernel(const float* __restrict__ src,
                                    __nv_bfloat16* __restrict__ hi,
                                    __nv_bfloat16* __restrict__ lo, int n)
{
    int i = blockIdx.x * 256 + threadIdx.x;
    if (i < n) {
        float v = src[i];
        __nv_bfloat16 h = __float2bfloat16_rn(v);
        hi[i] = h;
        lo[i] = __float2bfloat16_rn(v - __bfloat162float(h));
    }
}

__global__ void transpose_pair_kernel(const float* __restrict__ src,
                                      __nv_bfloat16* __restrict__ dhi,
                                      __nv_bfloat16* __restrict__ dlo, int R, int C)
{
    __shared__ float t[32][33];
    int c0 = blockIdx.x * 32, r0 = blockIdx.y * 32;
    int x = threadIdx.x, y = threadIdx.y;
    for (int i = 0; i < 32; i += 8)
        t[y + i][x] = src[(size_t)(r0 + y + i) * C + c0 + x];
    __syncthreads();
    for (int i = 0; i < 32; i += 8) {
        float v = t[x][y + i];
        __nv_bfloat16 h = __float2bfloat16_rn(v);
        size_t o = (size_t)(c0 + y + i) * R + r0 + x;
        dhi[o] = h;
        dlo[o] = __float2bfloat16_rn(v - __bfloat162float(h));
    }
}

// ----------------------------- bucket argmax (coalesced) --------------------
__global__ void bucket_kernel()
{
    int idx = blockIdx.x * 256 + threadIdx.x;
    int h = idx & 7;
    int t = (idx >> 3) & (T_LEN - 1);
    int bh = idx >> 16;
    const float4* p = (const float4*)(g_rv + ((size_t)bh * T_LEN + t) * 512 + h * 64);
    float maxv = -1e30f, minv = 1e30f;
    int imax = 0, imin = 0;
#pragma unroll
    for (int i = 0; i < 16; i++) {
        float4 q = p[i];
        float vv[4] = {q.x, q.y, q.z, q.w};
#pragma unroll
        for (int c = 0; c < 4; c++) {
            int j = i * 4 + c;
            if (vv[c] > maxv) { maxv = vv[c]; imax = j; }
            if (vv[c] < minv) { minv = vv[c]; imin = j; }
        }
    }
    int bi = (maxv >= -minv) ? imax : 64 + imin;
    g_buckets[(size_t)bh * HT + (size_t)h * T_LEN + t] = bi + h * NB;
}

__global__ void zero_counts_kernel()
{
    int idx = blockIdx.x * 256 + threadIdx.x;
    if (idx < BHD * NBTOT) g_counts[idx] = 0;
}

__global__ void hist_kernel()
{
    int idx = blockIdx.x * 256 + threadIdx.x;
    int bh = idx >> 16;
    atomicAdd(&g_counts[bh * NBTOT + g_buckets[idx]], 1);
}

__global__ void scan_kernel()
{
    __shared__ int s[NBTOT];
    int bh = blockIdx.x, t = threadIdx.x;
    int my = g_counts[bh * NBTOT + t];
    s[t] = my;
    __syncthreads();
    for (int d = 1; d < NBTOT; d <<= 1) {
        int v = (t >= d) ? s[t - d] : 0;
        __syncthreads();
        s[t] += v;
        __syncthreads();
    }
    g_offsets[bh * NBTOT + t] = s[t] - my;
}

__global__ void scatter_kernel()
{
    __shared__ int cnt[4][NB];
    int w = threadIdx.x >> 5, lane = threadIdx.x & 31;
    int wg = blockIdx.x * 4 + w;
    int bh = wg >> 3, h = wg & 7;
#pragma unroll
    for (int i = 0; i < 4; i++)
        cnt[w][lane * 4 + i] = g_offsets[bh * NBTOT + h * NB + lane * 4 + i];
    __syncwarp();
    const int* bk = g_buckets + (size_t)bh * HT + (size_t)h * T_LEN;
    int* stp = g_st + (size_t)bh * HT;
    int* unp = g_undo + (size_t)bh * HT + (size_t)h * T_LEN;
    for (int t0 = 0; t0 < T_LEN; t0 += 32) {
        int t = t0 + lane;
        int b = bk[t] - h * NB;
        unsigned mask = __match_any_sync(0xffffffffu, b);
        int lead = __ffs(mask) - 1;
        int pre = __popc(mask & ((1u << lane) - 1u));
        int base = 0;
        if (lane == lead) base = cnt[w][b];
        base = __shfl_sync(0xffffffffu, base, lead);
        int rnk = base + pre;
        if (lane == lead) cnt[w][b] = base + __popc(mask);
        stp[rnk] = t;
        unp[t] = rnk;
        __syncwarp();
    }
}

// ----------------------------- tensor-core chunked attention ----------------
// smem layout (bytes):
#define PT  136                 // bf16 pitch for mma tiles
#define SCP 132                 // fp32 pitch for scores
#define OFF_KHI 0
#define OFF_KLO 34816
#define OFF_VHI 69632
#define OFF_VLO 104448
#define OFF_PHI 139264          // q pair during scores; probs pair during pv
#define OFF_PLO 156672
#define OFF_SC  174080
#define OFF_POS 207872
#define OFF_PAD 208384
#define SMEM_ATT 208896

__global__ void __launch_bounds__(256) attn_kernel(const unsigned char* __restrict__ pm)
{
    extern __shared__ char sm[];
    uint32_t sb = smem_u32(sm);
    __nv_bfloat16* khi = (__nv_bfloat16*)(sm + OFF_KHI);
    __nv_bfloat16* klo = (__nv_bfloat16*)(sm + OFF_KLO);
    __nv_bfloat16* vhi = (__nv_bfloat16*)(sm + OFF_VHI);
    __nv_bfloat16* vlo = (__nv_bfloat16*)(sm + OFF_VLO);
    __nv_bfloat16* phi = (__nv_bfloat16*)(sm + OFF_PHI);
    __nv_bfloat16* plo = (__nv_bfloat16*)(sm + OFF_PLO);
    float* sc = (float*)(sm + OFF_SC);
    int* posk = (int*)(sm + OFF_POS);
    int* padk = (int*)(sm + OFF_PAD);

    int bh = blockIdx.y, c = blockIdx.x;
    int b = bh >> 3, h = bh & 7;
    int tid = threadIdx.x, lane = tid & 31, wid = tid >> 5;

    // phase 0: slot -> token positions + pad flags
    if (tid < 128) {
        int j = tid;
        int cprev = (c == 0) ? (NCHUNK - 1) : (c - 1);
        int slot = (j < BUCKETSZ) ? c * BUCKETSZ + j : cprev * BUCKETSZ + (j - BUCKETSZ);
        int pos = g_st[(size_t)bh * HT + slot];
        posk[j] = pos;
        padk[j] = pm[b * T_LEN + pos] ? 1 : 0;
    }
    __syncthreads();

    // phase 1: load qk rows (q scaled for r<64; k l2-normalized for all), v rows
    for (int rr = 0; rr < 16; rr++) {
        int r = wid * 16 + rr;
        int pos = posk[r];
        const float4* src = (const float4*)(g_qk + ((size_t)(b * T_LEN + pos)) * EMB + h * DH);
        float4 q4 = src[lane];
        float ss = q4.x * q4.x + q4.y * q4.y + q4.z * q4.z + q4.w * q4.w;
#pragma unroll
        for (int o = 16; o > 0; o >>= 1) ss += __shfl_xor_sync(0xffffffffu, ss, o);
        float rn = rsqrtf(fmaxf(ss, 1e-12f));
        {
            float k0v = q4.x * rn, k1v = q4.y * rn, k2v = q4.z * rn, k3v = q4.w * rn;
            float h0 = __bfloat162float(__float2bfloat16_rn(k0v));
            float h1 = __bfloat162float(__float2bfloat16_rn(k1v));
            float h2 = __bfloat162float(__float2bfloat16_rn(k2v));
            float h3 = __bfloat162float(__float2bfloat16_rn(k3v));
            uint32_t e = r * PT + lane * 4;
            *(uint2*)(khi + e) = make_uint2(packbf2(k0v, k1v), packbf2(k2v, k3v));
            *(uint2*)(klo + e) = make_uint2(packbf2(k0v - h0, k1v - h1), packbf2(k2v - h2, k3v - h3));
        }
        if (r < 64) {
            float q0 = q4.x * QSCALE, q1 = q4.y * QSCALE, q2 = q4.z * QSCALE, q3 = q4.w * QSCALE;
            float h0 = __bfloat162float(__float2bfloat16_rn(q0));
            float h1 = __bfloat162float(__float2bfloat16_rn(q1));
            float h2 = __bfloat162float(__float2bfloat16_rn(q2));
            float h3 = __bfloat162float(__float2bfloat16_rn(q3));
            uint32_t e = r * PT + lane * 4;
            *(uint2*)(phi + e) = make_uint2(packbf2(q0, q1), packbf2(q2, q3));
            *(uint2*)(plo + e) = make_uint2(packbf2(q0 - h0, q1 - h1), packbf2(q2 - h2, q3 - h3));
        }
        const float4* sv = (const float4*)(g_v + ((size_t)(b * T_LEN + pos)) * EMB + h * DH);
        float4 v4 = sv[lane];
        {
            float h0 = __bfloat162float(__float2bfloat16_rn(v4.x));
            float h1 = __bfloat162float(__float2bfloat16_rn(v4.y));
            float h2 = __bfloat162float(__float2bfloat16_rn(v4.z));
            float h3 = __bfloat162float(__float2bfloat16_rn(v4.w));
            uint32_t e = r * PT + lane * 4;
            *(uint2*)(vhi + e) = make_uint2(packbf2(v4.x, v4.y), packbf2(v4.z, v4.w));
            *(uint2*)(vlo + e) = make_uint2(packbf2(v4.x - h0, v4.y - h1), packbf2(v4.z - h2, v4.w - h3));
        }
    }
    __syncthreads();

    // phase 2: scores S[64][128] = q @ k^T, warp = (mt, nh): 16q x 64kv
    {
        int mt = wid & 3, nh = wid >> 2;
        float cS[8][4];
#pragma unroll
        for (int i = 0; i < 8; i++)
#pragma unroll
            for (int j = 0; j < 4; j++) cS[i][j] = 0.f;

        uint32_t g = lane >> 3, i2 = lane & 7;
#pragma unroll
        for (int ks = 0; ks < 8; ks++) {
            int k0 = ks * 16;
            uint32_t ah[4], al[4];
            uint32_t aoff = (uint32_t)(((mt * 16 + (lane & 15)) * PT + k0 + ((lane >> 4) << 3)) * 2);
            ldm_x4(ah, sb + OFF_PHI + aoff);
            ldm_x4(al, sb + OFF_PLO + aoff);
#pragma unroll
            for (int np = 0; np < 4; np++) {
                int n0 = nh * 64 + np * 16;
                uint32_t boff = (uint32_t)(((n0 + ((g >> 1) << 3) + i2) * PT + k0 + ((g & 1) << 3)) * 2);
                uint32_t bh4[4], bl4[4];
                ldm_x4(bh4, sb + OFF_KHI + boff);
                ldm_x4(bl4, sb + OFF_KLO + boff);
                mma16816(cS[np * 2], ah, bh4);
                mma16816(cS[np * 2], ah, bl4);
                mma16816(cS[np * 2], al, bh4);
                mma16816(cS[np * 2 + 1], ah, bh4 + 2);
                mma16816(cS[np * 2 + 1], ah, bl4 + 2);
                mma16816(cS[np * 2 + 1], al, bh4 + 2);
            }
        }
        // masked store to sc[q][kv]
        int q0 = mt * 16 + (lane >> 2);
        int pq0 = posk[q0], pq1 = posk[q0 + 8];
#pragma unroll
        for (int t8 = 0; t8 < 8; t8++) {
            int kvb = nh * 64 + t8 * 8 + ((lane & 3) << 1);
#pragma unroll
            for (int e = 0; e < 2; e++) {
                int kv = kvb + e;
                int pk = posk[kv], pd = padk[kv];
                float s0 = cS[t8][e];
                float s1 = cS[t8][2 + e];
                s0 = (pq0 == pk) ? -1e5f : (pd ? -1e9f : s0);
                s1 = (pq1 == pk) ? -1e5f : (pd ? -1e9f : s1);
                sc[q0 * SCP + kv] = s0;
                sc[(q0 + 8) * SCP + kv] = s1;
            }
        }
    }
    __syncthreads();

    // phase 3: softmax per q row (4 threads per row), write probs bf16 pair over q space
    {
        int q = tid >> 2, t4 = tid & 3;
        float vals[32];
        float m = -1e30f;
#pragma unroll
        for (int j = 0; j < 32; j++) {
            vals[j] = sc[q * SCP + t4 + 4 * j];
            m = fmaxf(m, vals[j]);
        }
        m = fmaxf(m, __shfl_xor_sync(0xffffffffu, m, 1));
        m = fmaxf(m, __shfl_xor_sync(0xffffffffu, m, 2));
        float Z = 0.f;
#pragma unroll
        for (int j = 0; j < 32; j++) Z += expf(vals[j] - m);
        Z += __shfl_xor_sync(0xffffffffu, Z, 1);
        Z += __shfl_xor_sync(0xffffffffu, Z, 2);
        float lse = m + logf(Z);
        if (t4 == 0) g_slog[(size_t)bh * HT + c * BUCKETSZ + q] = lse;
        __syncthreads();   // all sc reads done before overwriting phi/plo region? (phi != sc; ensures scores phase fully complete block-wide)
#pragma unroll
        for (int j = 0; j < 32; j++) {
            float p = expf(vals[j] - lse);
            float hp = __bfloat162float(__float2bfloat16_rn(p));
            int e = q * PT + t4 + 4 * j;
            phi[e] = __float2bfloat16_rn(p);
            plo[e] = __float2bfloat16_rn(p - hp);
        }
    }
    __syncthreads();

    // phase 4: O[64][128] = P @ V, warp = (mt, dh2): 16q x 64d
    {
        int mt = wid & 3, dh2 = wid >> 2;
        float cO[8][4];
#pragma unroll
        for (int i = 0; i < 8; i++)
#pragma unroll
            for (int j = 0; j < 4; j++) cO[i][j] = 0.f;

        uint32_t g = lane >> 3, i2 = lane & 7;
#pragma unroll
        for (int ks = 0; ks < 8; ks++) {
            int k0 = ks * 16;
            uint32_t ah[4], al[4];
            uint32_t aoff = (uint32_t)(((mt * 16 + (lane & 15)) * PT + k0 + ((lane >> 4) << 3)) * 2);
            ldm_x4(ah, sb + OFF_PHI + aoff);
            ldm_x4(al, sb + OFF_PLO + aoff);
#pragma unroll
            for (int dp = 0; dp < 4; dp++) {
                int d0 = dh2 * 64 + dp * 16;
                uint32_t boff = (uint32_t)(((k0 + ((g & 1) << 3) + i2) * PT + d0 + ((g >> 1) << 3)) * 2);
                uint32_t bh4[4], bl4[4];
                ldm_x4_t(bh4, sb + OFF_VHI + boff);
                ldm_x4_t(bl4, sb + OFF_VLO + boff);
                mma16816(cO[dp * 2], ah, bh4);
                mma16816(cO[dp * 2], ah, bl4);
                mma16816(cO[dp * 2], al, bh4);
                mma16816(cO[dp * 2 + 1], ah, bh4 + 2);
                mma16816(cO[dp * 2 + 1], ah, bl4 + 2);
                mma16816(cO[dp * 2 + 1], al, bh4 + 2);
            }
        }
        int q0 = mt * 16 + (lane >> 2);
        float* base0 = g_so + ((size_t)bh * HT + c * BUCKETSZ + q0) * DH;
        float* base1 = g_so + ((size_t)bh * HT + c * BUCKETSZ + q0 + 8) * DH;
#pragma unroll
        for (int t8 = 0; t8 < 8; t8++) {
            int d = dh2 * 64 + t8 * 8 + ((lane & 3) << 1);
            *(float2*)(base0 + d) = make_float2(cO[t8][0], cO[t8][1]);
            *(float2*)(base1 + d) = make_float2(cO[t8][2], cO[t8][3]);
        }
    }
}

// ----------------------------- combine hash rounds --------------------------
__global__ void combine_kernel()
{
    int gw = (blockIdx.x * 256 + threadIdx.x) >> 5;
    int lane = threadIdx.x & 31;
    int bh = gw >> 13;
    int pos = gw & (T_LEN - 1);
    int b = bh >> 3, hh = bh & 7;

    int s = 0;
    float l = -1e30f;
    if (lane < N_HASH) {
        s = g_undo[(size_t)bh * HT + (size_t)lane * T_LEN + pos];
        l = g_slog[(size_t)bh * HT + s];
    }
    float m = l;
#pragma unroll
    for (int o = 16; o > 0; o >>= 1) m = fmaxf(m, __shfl_xor_sync(0xffffffffu, m, o));
    float e = (lane < N_HASH) ? expf(l - m) : 0.f;
    float Z = e;
#pragma unroll
    for (int o = 16; o > 0; o >>= 1) Z += __shfl_xor_sync(0xffffffffu, Z, o);

    float4 acc = make_float4(0.f, 0.f, 0.f, 0.f);
#pragma unroll
    for (int h2 = 0; h2 < N_HASH; h2++) {
        int sh = __shfl_sync(0xffffffffu, s, h2);
        float wv = __shfl_sync(0xffffffffu, e, h2) / Z;
        const float4* row = (const float4*)(g_so + ((size_t)bh * HT + sh) * DH);
        float4 t = row[lane];
        acc.x = fmaf(wv, t.x, acc.x);
        acc.y = fmaf(wv, t.y, acc.y);
        acc.z = fmaf(wv, t.z, acc.z);
        acc.w = fmaf(wv, t.w, acc.w);
    }
    size_t off = ((size_t)(b * T_LEN + pos)) * EMB + hh * DH + lane * 4;
    float fv[4] = {acc.x, acc.y, acc.z, acc.w};
    __nv_bfloat16 hi[4]; float lo[4];
#pragma unroll
    for (int u = 0; u < 4; u++) { hi[u] = __float2bfloat16_rn(fv[u]); lo[u] = fv[u] - __bfloat162float(hi[u]); }
    ((__nv_bfloat162*)(g_attn_hi + off))[0] = __nv_bfloat162(hi[0], hi[1]);
    ((__nv_bfloat162*)(g_attn_hi + off))[1] = __nv_bfloat162(hi[2], hi[3]);
    ((__nv_bfloat162*)(g_attn_lo + off))[0] = __floats2bfloat162_rn(lo[0], lo[1]);
    ((__nv_bfloat162*)(g_attn_lo + off))[1] = __floats2bfloat162_rn(lo[2], lo[3]);
}

// ----------------------------- launcher -------------------------------------
extern "C" void kernel_launch(void* const* d_in, const int* in_sizes, int n_in,
                              void* d_out, int out_size)
{
    const float* x = (const float*)d_in[0];
    const unsigned char* pm = (const unsigned char*)d_in[1];
    const float* rot = (const float*)d_in[2];
    const float* Wqk = (const float*)d_in[3];
    const float* Wv = (const float*)d_in[4];
    const float* Wout = (const float*)d_in[5];
    const float* bout = (const float*)d_in[6];
    float* out = (float*)d_out;

    float *qk, *v, *rv;
    __nv_bfloat16 *xhi, *xlo, *athi, *atlo;
    __nv_bfloat16 *wvh, *wvl, *woh, *wol;
    cudaGetSymbolAddress((void**)&qk, g_qk);
    cudaGetSymbolAddress((void**)&v, g_v);
    cudaGetSymbolAddress((void**)&rv, g_rv);
    cudaGetSymbolAddress((void**)&xhi, g_x_hi);
    cudaGetSymbolAddress((void**)&xlo, g_x_lo);
    cudaGetSymbolAddress((void**)&athi, g_attn_hi);
    cudaGetSymbolAddress((void**)&atlo, g_attn_lo);
    cudaGetSymbolAddress((void**)&wvh, g_wvT_hi);
    cudaGetSymbolAddress((void**)&wvl, g_wvT_lo);
    cudaGetSymbolAddress((void**)&woh, g_woutT_hi);
    cudaGetSymbolAddress((void**)&wol, g_woutT_lo);

    cudaFuncSetAttribute(mma_gemm, cudaFuncAttributeMaxDynamicSharedMemorySize, GEMM_SMEM);
    cudaFuncSetAttribute(attn_kernel, cudaFuncAttributeMaxDynamicSharedMemorySize, SMEM_ATT);

    convert_pair_kernel<<<(BT * EMB) / 256, 256>>>(x, xhi, xlo, BT * EMB);
    transpose_pair_kernel<<<dim3(EMB / 32, EMB / 32), dim3(32, 8)>>>(Wv, wvh, wvl, EMB, EMB);
    transpose_pair_kernel<<<dim3(EMB / 32, EMB / 32), dim3(32, 8)>>>(Wout, woh, wol, EMB, EMB);

    // qk = x @ Wqk — EXACT fp32 sequential-k (bucket path)
    gemm_kernel<<<dim3(EMB / GBN, BT / GBM, 1), 256>>>(x, Wqk, qk, nullptr,
        BT, EMB, EMB, EMB, EMB, EMB, 0, 0, 1, 0);
    // v = x @ Wv — tensor cores
    mma_gemm<<<dim3(EMB / 128, BT / 128, 1), 256, GEMM_SMEM>>>(
        xhi, xlo, wvh, wvl, v, nullptr, EMB, EMB, EMB, EMB);
    // rv = qk_head @ rot — EXACT fp32
    gemm_kernel<<<dim3(512 / GBN, T_LEN / GBM, BHD), 256>>>(qk, rot, rv, nullptr,
        T_LEN, 512, DH, EMB, 512, 512,
        (long long)T_LEN * EMB, DH, N_HASH, (long long)T_LEN * 512);

    bucket_kernel<<<(BHD * HT) / 256, 256>>>();
    zero_counts_kernel<<<(BHD * NBTOT + 255) / 256, 256>>>();
    hist_kernel<<<(BHD * HT) / 256, 256>>>();
    scan_kernel<<<BHD, NBTOT>>>();
    scatter_kernel<<<(BHD * N_HASH) / 4, 128>>>();

    attn_kernel<<<dim3(NCHUNK, BHD), 256, SMEM_ATT>>>(pm);

    combine_kernel<<<(BHD * T_LEN) / 8, 256>>>();

    // out = attn @ Wout + bout — tensor cores
    mma_gemm<<<dim3(EMB / 128, BT / 128, 1), 256, GEMM_SMEM>>>(
        athi, atlo, woh, wol, out, bout, EMB, EMB, EMB, EMB);
}

// round 6
// speedup vs baseline: 1.9614x; 1.1470x over previous
#include <cuda_runtime.h>
#include <cuda_bf16.h>
#include <cstdint>
#include <math.h>

#define T_LEN   8192
#define B_SZ    2
#define N_HEADS 8
#define DH      128
#define EMB     1024
#define BHD     16          // B * HEADS
#define N_HASH  8
#define NB      128         // buckets per hash
#define NBTOT   1024        // N_HASH * NB
#define BUCKETSZ 64
#define NCHUNK  1024        // per bh
#define HT      65536       // N_HASH * T
#define BT      16384       // B * T
#define QSCALE  0.08838834764831843f

// ----------------------------- scratch (static device memory; no allocs) ---
__device__ float g_qk[(size_t)BT * EMB];            // fp32 (exact path + attention)
__device__ float g_v[(size_t)BT * EMB];
__device__ __nv_bfloat16 g_x_hi[(size_t)BT * EMB];
__device__ __nv_bfloat16 g_x_lo[(size_t)BT * EMB];
__device__ __nv_bfloat16 g_attn_hi[(size_t)BT * EMB];
__device__ __nv_bfloat16 g_attn_lo[(size_t)BT * EMB];
__device__ __nv_bfloat16 g_wvT_hi[EMB * EMB];
__device__ __nv_bfloat16 g_wvT_lo[EMB * EMB];
__device__ __nv_bfloat16 g_woutT_hi[EMB * EMB];
__device__ __nv_bfloat16 g_woutT_lo[EMB * EMB];
__device__ float g_rv[(size_t)BHD * T_LEN * 512];
__device__ int   g_buckets[(size_t)BHD * HT];
__device__ int   g_counts[BHD * NBTOT];
__device__ int   g_offsets[BHD * NBTOT];
__device__ int   g_st[(size_t)BHD * HT];
__device__ int   g_undo[(size_t)BHD * HT];
__device__ float g_so[(size_t)BHD * HT * DH];
__device__ float g_slog[(size_t)BHD * HT];

// ----------------------------- cp.async helpers -----------------------------
__device__ __forceinline__ void cp_async16(uint32_t dst, const void* src) {
    asm volatile("cp.async.ca.shared.global [%0], [%1], 16;" :: "r"(dst), "l"(src));
}
#define CP_COMMIT() asm volatile("cp.async.commit_group;" ::: "memory")
#define CP_WAIT0()  asm volatile("cp.async.wait_group 0;" ::: "memory")

// ----------------------------- exact fp32 GEMM (sequential-k; bucket path) --
// 128x128 tile, 2-stage cp.async pipeline. Per-output accumulation is a single
// fp32 accumulator in strictly ascending k -> bitwise identical to prior rounds.
#define GBM 128
#define GBN 128
#define GBK 16

__global__ void __launch_bounds__(256, 2) gemm_kernel(
    const float* __restrict__ A, const float* __restrict__ Bm,
    float* __restrict__ C, const float* __restrict__ bias,
    int M, int N, int K, int lda, int ldb, int ldc,
    long long sAouter, long long sAinner, int innerDiv,
    long long sC)
{
    __shared__ float As[2][GBK][GBM + 4];
    __shared__ float Bs[2][GBK][GBN];
    int z = blockIdx.z;
    const float* Ab = A + (long long)(z / innerDiv) * sAouter + (long long)(z % innerDiv) * sAinner;
    float* Cb = C + (long long)z * sC;
    int row0 = blockIdx.y * GBM;
    int col0 = blockIdx.x * GBN;
    int tid = threadIdx.x;
    int tx = tid & 15, ty = tid >> 4;

    float acc[8][8];
#pragma unroll
    for (int i = 0; i < 8; i++)
#pragma unroll
        for (int j = 0; j < 8; j++) acc[i][j] = 0.f;

    float4 areg[2];

    // prologue: stage 0
#pragma unroll
    for (int i = 0; i < 2; i++) {
        int idx = tid + (i << 8);
        int row = idx >> 2, ks4 = (idx & 3) << 2;
        areg[i] = *(const float4*)&Ab[(size_t)(row0 + row) * lda + ks4];
    }
#pragma unroll
    for (int i = 0; i < 2; i++) {
        int idx = tid + (i << 8);
        int kk = idx >> 5, c4 = (idx & 31) << 2;
        cp_async16((uint32_t)__cvta_generic_to_shared(&Bs[0][kk][c4]),
                   &Bm[(size_t)kk * ldb + col0 + c4]);
    }
    CP_COMMIT();
#pragma unroll
    for (int i = 0; i < 2; i++) {
        int idx = tid + (i << 8);
        int row = idx >> 2, ks4 = (idx & 3) << 2;
        As[0][ks4 + 0][row] = areg[i].x;
        As[0][ks4 + 1][row] = areg[i].y;
        As[0][ks4 + 2][row] = areg[i].z;
        As[0][ks4 + 3][row] = areg[i].w;
    }
    CP_WAIT0();
    __syncthreads();

    int cur = 0;
    for (int k0 = 0; k0 < K; k0 += GBK) {
        int nxt = cur ^ 1;
        bool has = (k0 + GBK) < K;
        if (has) {
#pragma unroll
            for (int i = 0; i < 2; i++) {
                int idx = tid + (i << 8);
                int row = idx >> 2, ks4 = (idx & 3) << 2;
                areg[i] = *(const float4*)&Ab[(size_t)(row0 + row) * lda + k0 + GBK + ks4];
            }
#pragma unroll
            for (int i = 0; i < 2; i++) {
                int idx = tid + (i << 8);
                int kk = idx >> 5, c4 = (idx & 31) << 2;
                cp_async16((uint32_t)__cvta_generic_to_shared(&Bs[nxt][kk][c4]),
                           &Bm[(size_t)(k0 + GBK + kk) * ldb + col0 + c4]);
            }
            CP_COMMIT();
        }
#pragma unroll
        for (int kk = 0; kk < GBK; kk++) {
            float4 a0 = *(float4*)&As[cur][kk][ty * 4];
            float4 a1 = *(float4*)&As[cur][kk][64 + ty * 4];
            float4 b0 = *(float4*)&Bs[cur][kk][tx * 4];
            float4 b1 = *(float4*)&Bs[cur][kk][64 + tx * 4];
            float av[8] = {a0.x, a0.y, a0.z, a0.w, a1.x, a1.y, a1.z, a1.w};
            float bv[8] = {b0.x, b0.y, b0.z, b0.w, b1.x, b1.y, b1.z, b1.w};
#pragma unroll
            for (int i = 0; i < 8; i++)
#pragma unroll
                for (int j = 0; j < 8; j++) acc[i][j] = fmaf(av[i], bv[j], acc[i][j]);
        }
        if (has) {
#pragma unroll
            for (int i = 0; i < 2; i++) {
                int idx = tid + (i << 8);
                int row = idx >> 2, ks4 = (idx & 3) << 2;
                As[nxt][ks4 + 0][row] = areg[i].x;
                As[nxt][ks4 + 1][row] = areg[i].y;
                As[nxt][ks4 + 2][row] = areg[i].z;
                As[nxt][ks4 + 3][row] = areg[i].w;
            }
            CP_WAIT0();
        }
        __syncthreads();
        cur = nxt;
    }
#pragma unroll
    for (int ih = 0; ih < 2; ih++)
#pragma unroll
        for (int i = 0; i < 4; i++) {
            int r = row0 + ih * 64 + ty * 4 + i;
#pragma unroll
            for (int jh = 0; jh < 2; jh++) {
                int c = col0 + jh * 64 + tx * 4;
                float4 o;
                o.x = acc[ih * 4 + i][jh * 4 + 0];
                o.y = acc[ih * 4 + i][jh * 4 + 1];
                o.z = acc[ih * 4 + i][jh * 4 + 2];
                o.w = acc[ih * 4 + i][jh * 4 + 3];
                if (bias) { o.x += bias[c]; o.y += bias[c + 1]; o.z += bias[c + 2]; o.w += bias[c + 3]; }
                *(float4*)&Cb[(size_t)r * ldc + c] = o;
            }
        }
}

// ----------------------------- mma helpers (portable PTX, sm_80+) ----------
__device__ __forceinline__ uint32_t smem_u32(const void* p) {
    uint32_t a;
    asm("{ .reg .u64 t; cvta.to.shared.u64 t, %1; cvt.u32.u64 %0, t; }" : "=r"(a) : "l"(p));
    return a;
}
__device__ __forceinline__ void ldm_x4(uint32_t* r, uint32_t addr) {
    asm volatile("ldmatrix.sync.aligned.m8n8.x4.shared.b16 {%0,%1,%2,%3}, [%4];"
        : "=r"(r[0]), "=r"(r[1]), "=r"(r[2]), "=r"(r[3]) : "r"(addr));
}
__device__ __forceinline__ void ldm_x4_t(uint32_t* r, uint32_t addr) {
    asm volatile("ldmatrix.sync.aligned.m8n8.x4.trans.shared.b16 {%0,%1,%2,%3}, [%4];"
        : "=r"(r[0]), "=r"(r[1]), "=r"(r[2]), "=r"(r[3]) : "r"(addr));
}
__device__ __forceinline__ void ldm_x2(uint32_t* r, uint32_t addr) {
    asm volatile("ldmatrix.sync.aligned.m8n8.x2.shared.b16 {%0,%1}, [%2];"
        : "=r"(r[0]), "=r"(r[1]) : "r"(addr));
}
__device__ __forceinline__ void mma16816(float* d, const uint32_t* a, const uint32_t* b) {
    asm volatile("mma.sync.aligned.m16n8k16.row.col.f32.bf16.bf16.f32 "
        "{%0,%1,%2,%3}, {%4,%5,%6,%7}, {%8,%9}, {%0,%1,%2,%3};"
        : "+f"(d[0]), "+f"(d[1]), "+f"(d[2]), "+f"(d[3])
        : "r"(a[0]), "r"(a[1]), "r"(a[2]), "r"(a[3]), "r"(b[0]), "r"(b[1]));
}
__device__ __forceinline__ uint32_t packbf2(float x, float y) {
    __nv_bfloat162 p(__float2bfloat16_rn(x), __float2bfloat16_rn(y));
    return *(uint32_t*)&p;
}

// ----------------------------- bf16-split tensor-core GEMM (smooth path) ----
#define SA_HI 0
#define SA_LO 16384
#define SB_HI 32768
#define SB_LO 49152
#define GEMM_SMEM 65536

__global__ void __launch_bounds__(256) mma_gemm(
    const __nv_bfloat16* __restrict__ Ahi, const __nv_bfloat16* __restrict__ Alo,
    const __nv_bfloat16* __restrict__ Bhi, const __nv_bfloat16* __restrict__ Blo,
    float* __restrict__ C, const float* __restrict__ bias,
    int K, int lda, int ldb, int ldc)
{
    extern __shared__ char sm[];
    uint32_t sb = smem_u32(sm);
    int tid = threadIdx.x, lane = tid & 31, wid = tid >> 5;
    int wm = wid & 1, wn = wid >> 1;

    int m0 = blockIdx.y * 128, n0 = blockIdx.x * 128;

    float acc[4][4][4];
#pragma unroll
    for (int mt = 0; mt < 4; mt++)
#pragma unroll
        for (int nt = 0; nt < 4; nt++)
#pragma unroll
            for (int i = 0; i < 4; i++) acc[mt][nt][i] = 0.f;

    int nch = K >> 6;
    for (int ch = 0; ch < nch; ch++) {
        int k0 = ch << 6;
        const __nv_bfloat16* Abh = Ahi + (size_t)m0 * lda + k0;
        const __nv_bfloat16* Abl = Alo + (size_t)m0 * lda + k0;
        const __nv_bfloat16* Bbh = Bhi + (size_t)n0 * ldb + k0;
        const __nv_bfloat16* Bbl = Blo + (size_t)n0 * ldb + k0;
#pragma unroll
        for (int i = 0; i < 4; i++) {
            int idx = tid + (i << 8);
            int row = idx >> 3, seg = idx & 7;
            uint32_t off = (uint32_t)((row << 7) + (seg << 4));
            uint32_t sw = off ^ ((off >> 3) & 0x70);
            *(uint4*)(sm + SA_HI + sw) = *(const uint4*)(Abh + (size_t)row * lda + (seg << 3));
            *(uint4*)(sm + SA_LO + sw) = *(const uint4*)(Abl + (size_t)row * lda + (seg << 3));
            *(uint4*)(sm + SB_HI + sw) = *(const uint4*)(Bbh + (size_t)row * ldb + (seg << 3));
            *(uint4*)(sm + SB_LO + sw) = *(const uint4*)(Bbl + (size_t)row * ldb + (seg << 3));
        }
        __syncthreads();
#pragma unroll
        for (int kk = 0; kk < 4; kk++) {
            uint32_t afh[4][4], afl[4][4];
#pragma unroll
            for (int mt = 0; mt < 4; mt++) {
                int row = wm * 64 + mt * 16 + (lane & 15);
                uint32_t off = (uint32_t)((row << 7) + (kk << 5) + ((lane >> 4) << 4));
                uint32_t sw = off ^ ((off >> 3) & 0x70);
                ldm_x4(afh[mt], sb + SA_HI + sw);
                ldm_x4(afl[mt], sb + SA_LO + sw);
            }
            uint32_t bfh[4][2], bfl[4][2];
#pragma unroll
            for (int nt = 0; nt < 4; nt++) {
                int row = wn * 32 + nt * 8 + (lane & 7);
                uint32_t off = (uint32_t)((row << 7) + (kk << 5) + (((lane >> 3) & 1) << 4));
                uint32_t sw = off ^ ((off >> 3) & 0x70);
                ldm_x2(bfh[nt], sb + SB_HI + sw);
                ldm_x2(bfl[nt], sb + SB_LO + sw);
            }
#pragma unroll
            for (int mt = 0; mt < 4; mt++)
#pragma unroll
                for (int nt = 0; nt < 4; nt++) {
                    mma16816(acc[mt][nt], afh[mt], bfh[nt]);
                    mma16816(acc[mt][nt], afh[mt], bfl[nt]);
                    mma16816(acc[mt][nt], afl[mt], bfh[nt]);
                }
        }
        __syncthreads();
    }

#pragma unroll
    for (int mt = 0; mt < 4; mt++) {
#pragma unroll
        for (int nt = 0; nt < 4; nt++) {
            int c = n0 + wn * 32 + nt * 8 + ((lane & 3) << 1);
#pragma unroll
            for (int half = 0; half < 2; half++) {
                int r = m0 + wm * 64 + mt * 16 + (lane >> 2) + half * 8;
                float v0 = acc[mt][nt][half * 2 + 0];
                float v1 = acc[mt][nt][half * 2 + 1];
                if (bias) { v0 += bias[c]; v1 += bias[c + 1]; }
                *(float2*)(C + (size_t)r * ldc + c) = make_float2(v0, v1);
            }
        }
    }
}

// ----------------------------- conversions ----------------------------------
__global__ void convert_pair_kernel(const float* __restrict__ src,
                                    __nv_bfloat16* __restrict__ hi,
                                    __nv_bfloat16* __restrict__ lo, int n)
{
    int i = blockIdx.x * 256 + threadIdx.x;
    if (i < n) {
        float v = src[i];
        __nv_bfloat16 h = __float2bfloat16_rn(v);
        hi[i] = h;
        lo[i] = __float2bfloat16_rn(v - __bfloat162float(h));
    }
}

__global__ void transpose_pair_kernel(const float* __restrict__ src,
                                      __nv_bfloat16* __restrict__ dhi,
                                      __nv_bfloat16* __restrict__ dlo, int R, int C)
{
    __shared__ float t[32][33];
    int c0 = blockIdx.x * 32, r0 = blockIdx.y * 32;
    int x = threadIdx.x, y = threadIdx.y;
    for (int i = 0; i < 32; i += 8)
        t[y + i][x] = src[(size_t)(r0 + y + i) * C + c0 + x];
    __syncthreads();
    for (int i = 0; i < 32; i += 8) {
        float v = t[x][y + i];
        __nv_bfloat16 h = __float2bfloat16_rn(v);
        size_t o = (size_t)(c0 + y + i) * R + r0 + x;
        dhi[o] = h;
        dlo[o] = __float2bfloat16_rn(v - __bfloat162float(h));
    }
}

// ----------------------------- bucket argmax (coalesced) --------------------
__global__ void bucket_kernel()
{
    int idx = blockIdx.x * 256 + threadIdx.x;
    int h = idx & 7;
    int t = (idx >> 3) & (T_LEN - 1);
    int bh = idx >> 16;
    const float4* p = (const float4*)(g_rv + ((size_t)bh * T_LEN + t) * 512 + h * 64);
    float maxv = -1e30f, minv = 1e30f;
    int imax = 0, imin = 0;
#pragma unroll
    for (int i = 0; i < 16; i++) {
        float4 q = p[i];
        float vv[4] = {q.x, q.y, q.z, q.w};
#pragma unroll
        for (int c = 0; c < 4; c++) {
            int j = i * 4 + c;
            if (vv[c] > maxv) { maxv = vv[c]; imax = j; }
            if (vv[c] < minv) { minv = vv[c]; imin = j; }
        }
    }
    int bi = (maxv >= -minv) ? imax : 64 + imin;
    g_buckets[(size_t)bh * HT + (size_t)h * T_LEN + t] = bi + h * NB;
}

__global__ void zero_counts_kernel()
{
    int idx = blockIdx.x * 256 + threadIdx.x;
    if (idx < BHD * NBTOT) g_counts[idx] = 0;
}

__global__ void hist_kernel()
{
    int idx = blockIdx.x * 256 + threadIdx.x;
    int bh = idx >> 16;
    atomicAdd(&g_counts[bh * NBTOT + g_buckets[idx]], 1);
}

__global__ void scan_kernel()
{
    __shared__ int s[NBTOT];
    int bh = blockIdx.x, t = threadIdx.x;
    int my = g_counts[bh * NBTOT + t];
    s[t] = my;
    __syncthreads();
    for (int d = 1; d < NBTOT; d <<= 1) {
        int v = (t >= d) ? s[t - d] : 0;
        __syncthreads();
        s[t] += v;
        __syncthreads();
    }
    g_offsets[bh * NBTOT + t] = s[t] - my;
}

__global__ void scatter_kernel()
{
    __shared__ int cnt[4][NB];
    int w = threadIdx.x >> 5, lane = threadIdx.x & 31;
    int wg = blockIdx.x * 4 + w;
    int bh = wg >> 3, h = wg & 7;
#pragma unroll
    for (int i = 0; i < 4; i++)
        cnt[w][lane * 4 + i] = g_offsets[bh * NBTOT + h * NB + lane * 4 + i];
    __syncwarp();
    const int* bk = g_buckets + (size_t)bh * HT + (size_t)h * T_LEN;
    int* stp = g_st + (size_t)bh * HT;
    int* unp = g_undo + (size_t)bh * HT + (size_t)h * T_LEN;
    for (int t0 = 0; t0 < T_LEN; t0 += 32) {
        int t = t0 + lane;
        int b = bk[t] - h * NB;
        unsigned mask = __match_any_sync(0xffffffffu, b);
        int lead = __ffs(mask) - 1;
        int pre = __popc(mask & ((1u << lane) - 1u));
        int base = 0;
        if (lane == lead) base = cnt[w][b];
        base = __shfl_sync(0xffffffffu, base, lead);
        int rnk = base + pre;
        if (lane == lead) cnt[w][b] = base + __popc(mask);
        stp[rnk] = t;
        unp[t] = rnk;
        __syncwarp();
    }
}

// ----------------------------- tensor-core chunked attention ----------------
// smem (bytes); 104KB total -> 2 CTAs/SM.
#define PT  136                 // bf16 pitch for mma tiles
#define OFF_KV_HI 0             // k pair during scores, v pair during PV
#define OFF_KV_LO 34816
#define OFF_P_HI  69632         // q pair during scores; probs pair during PV
#define OFF_P_LO  87040
#define OFF_REDM  104448        // [64][2] floats
#define OFF_REDS  104960
#define OFF_POS   105472
#define OFF_PAD   105984
#define SMEM_ATT  106496

__global__ void __launch_bounds__(256, 2) attn_kernel(const unsigned char* __restrict__ pm)
{
    extern __shared__ char sm[];
    uint32_t sb = smem_u32(sm);
    __nv_bfloat16* kvhi = (__nv_bfloat16*)(sm + OFF_KV_HI);
    __nv_bfloat16* kvlo = (__nv_bfloat16*)(sm + OFF_KV_LO);
    __nv_bfloat16* phi = (__nv_bfloat16*)(sm + OFF_P_HI);
    __nv_bfloat16* plo = (__nv_bfloat16*)(sm + OFF_P_LO);
    float* redM = (float*)(sm + OFF_REDM);
    float* redS = (float*)(sm + OFF_REDS);
    int* posk = (int*)(sm + OFF_POS);
    int* padk = (int*)(sm + OFF_PAD);

    int bh = blockIdx.y, c = blockIdx.x;
    int b = bh >> 3, h = bh & 7;
    int tid = threadIdx.x, lane = tid & 31, wid = tid >> 5;

    // phase 0: slot -> token positions + pad flags
    if (tid < 128) {
        int j = tid;
        int cprev = (c == 0) ? (NCHUNK - 1) : (c - 1);
        int slot = (j < BUCKETSZ) ? c * BUCKETSZ + j : cprev * BUCKETSZ + (j - BUCKETSZ);
        int pos = g_st[(size_t)bh * HT + slot];
        posk[j] = pos;
        padk[j] = pm[b * T_LEN + pos] ? 1 : 0;
    }
    __syncthreads();

    // phase 1: load qk rows (k normalized for all 128; q scaled for r<64)
    for (int rr = 0; rr < 16; rr++) {
        int r = wid * 16 + rr;
        int pos = posk[r];
        const float4* src = (const float4*)(g_qk + ((size_t)(b * T_LEN + pos)) * EMB + h * DH);
        float4 q4 = src[lane];
        float ss = q4.x * q4.x + q4.y * q4.y + q4.z * q4.z + q4.w * q4.w;
#pragma unroll
        for (int o = 16; o > 0; o >>= 1) ss += __shfl_xor_sync(0xffffffffu, ss, o);
        float rn = rsqrtf(fmaxf(ss, 1e-12f));
        {
            float k0v = q4.x * rn, k1v = q4.y * rn, k2v = q4.z * rn, k3v = q4.w * rn;
            float h0 = __bfloat162float(__float2bfloat16_rn(k0v));
            float h1 = __bfloat162float(__float2bfloat16_rn(k1v));
            float h2 = __bfloat162float(__float2bfloat16_rn(k2v));
            float h3 = __bfloat162float(__float2bfloat16_rn(k3v));
            uint32_t e = r * PT + lane * 4;
            *(uint2*)(kvhi + e) = make_uint2(packbf2(k0v, k1v), packbf2(k2v, k3v));
            *(uint2*)(kvlo + e) = make_uint2(packbf2(k0v - h0, k1v - h1), packbf2(k2v - h2, k3v - h3));
        }
        if (r < 64) {
            float q0 = q4.x * QSCALE, q1 = q4.y * QSCALE, q2 = q4.z * QSCALE, q3 = q4.w * QSCALE;
            float h0 = __bfloat162float(__float2bfloat16_rn(q0));
            float h1 = __bfloat162float(__float2bfloat16_rn(q1));
            float h2 = __bfloat162float(__float2bfloat16_rn(q2));
            float h3 = __bfloat162float(__float2bfloat16_rn(q3));
            uint32_t e = r * PT + lane * 4;
            *(uint2*)(phi + e) = make_uint2(packbf2(q0, q1), packbf2(q2, q3));
            *(uint2*)(plo + e) = make_uint2(packbf2(q0 - h0, q1 - h1), packbf2(q2 - h2, q3 - h3));
        }
    }
    __syncthreads();

    // phase 2: scores S[64][128] = q @ k^T, warp = (mt, nh): 16q x 64kv
    int mt = wid & 3, nh = wid >> 2;
    float cS[8][4];
#pragma unroll
    for (int i = 0; i < 8; i++)
#pragma unroll
        for (int j = 0; j < 4; j++) cS[i][j] = 0.f;
    {
        uint32_t g = lane >> 3, i2 = lane & 7;
#pragma unroll
        for (int ks = 0; ks < 8; ks++) {
            int k0 = ks * 16;
            uint32_t ah[4], al[4];
            uint32_t aoff = (uint32_t)(((mt * 16 + (lane & 15)) * PT + k0 + ((lane >> 4) << 3)) * 2);
            ldm_x4(ah, sb + OFF_P_HI + aoff);
            ldm_x4(al, sb + OFF_P_LO + aoff);
#pragma unroll
            for (int np = 0; np < 4; np++) {
                int n0 = nh * 64 + np * 16;
                uint32_t boff = (uint32_t)(((n0 + ((g >> 1) << 3) + i2) * PT + k0 + ((g & 1) << 3)) * 2);
                uint32_t bh4[4], bl4[4];
                ldm_x4(bh4, sb + OFF_KV_HI + boff);
                ldm_x4(bl4, sb + OFF_KV_LO + boff);
                mma16816(cS[np * 2], ah, bh4);
                mma16816(cS[np * 2], ah, bl4);
                mma16816(cS[np * 2], al, bh4);
                mma16816(cS[np * 2 + 1], ah, bh4 + 2);
                mma16816(cS[np * 2 + 1], ah, bl4 + 2);
                mma16816(cS[np * 2 + 1], al, bh4 + 2);
            }
        }
    }

    // masks in-register
    int q0 = mt * 16 + (lane >> 2);
    {
        int pq0 = posk[q0], pq1 = posk[q0 + 8];
#pragma unroll
        for (int t8 = 0; t8 < 8; t8++) {
            int kvb = nh * 64 + t8 * 8 + ((lane & 3) << 1);
#pragma unroll
            for (int e = 0; e < 2; e++) {
                int kv = kvb + e;
                int pk = posk[kv], pd = padk[kv];
                cS[t8][e]     = (pq0 == pk) ? -1e5f : (pd ? -1e9f : cS[t8][e]);
                cS[t8][2 + e] = (pq1 == pk) ? -1e5f : (pd ? -1e9f : cS[t8][2 + e]);
            }
        }
    }

    // phase 3: softmax in registers with tiny smem cross-warp reductions
    float lseA, lseB;
    {
        float mA = -1e30f, mB = -1e30f;
#pragma unroll
        for (int t8 = 0; t8 < 8; t8++) {
            mA = fmaxf(mA, fmaxf(cS[t8][0], cS[t8][1]));
            mB = fmaxf(mB, fmaxf(cS[t8][2], cS[t8][3]));
        }
        mA = fmaxf(mA, __shfl_xor_sync(0xffffffffu, mA, 1));
        mA = fmaxf(mA, __shfl_xor_sync(0xffffffffu, mA, 2));
        mB = fmaxf(mB, __shfl_xor_sync(0xffffffffu, mB, 1));
        mB = fmaxf(mB, __shfl_xor_sync(0xffffffffu, mB, 2));
        if ((lane & 3) == 0) {
            redM[q0 * 2 + nh] = mA;
            redM[(q0 + 8) * 2 + nh] = mB;
        }
        __syncthreads();            // also guarantees all mma reads of phi/kv done
        float MA = fmaxf(redM[q0 * 2], redM[q0 * 2 + 1]);
        float MB = fmaxf(redM[(q0 + 8) * 2], redM[(q0 + 8) * 2 + 1]);
        float sA = 0.f, sB = 0.f;
#pragma unroll
        for (int t8 = 0; t8 < 8; t8++) {
            sA += expf(cS[t8][0] - MA) + expf(cS[t8][1] - MA);
            sB += expf(cS[t8][2] - MB) + expf(cS[t8][3] - MB);
        }
        sA += __shfl_xor_sync(0xffffffffu, sA, 1);
        sA += __shfl_xor_sync(0xffffffffu, sA, 2);
        sB += __shfl_xor_sync(0xffffffffu, sB, 1);
        sB += __shfl_xor_sync(0xffffffffu, sB, 2);
        if ((lane & 3) == 0) {
            redS[q0 * 2 + nh] = sA;
            redS[(q0 + 8) * 2 + nh] = sB;
        }
        __syncthreads();
        float ZA = redS[q0 * 2] + redS[q0 * 2 + 1];
        float ZB = redS[(q0 + 8) * 2] + redS[(q0 + 8) * 2 + 1];
        lseA = MA + logf(ZA);
        lseB = MB + logf(ZB);
        if (nh == 0 && (lane & 3) == 0) {
            g_slog[(size_t)bh * HT + c * BUCKETSZ + q0] = lseA;
            g_slog[(size_t)bh * HT + c * BUCKETSZ + q0 + 8] = lseB;
        }
        // write probs bf16 pair into P buffer (q no longer needed)
#pragma unroll
        for (int t8 = 0; t8 < 8; t8++) {
            int col = nh * 64 + t8 * 8 + ((lane & 3) << 1);
            float pA0 = expf(cS[t8][0] - lseA), pA1 = expf(cS[t8][1] - lseA);
            float pB0 = expf(cS[t8][2] - lseB), pB1 = expf(cS[t8][3] - lseB);
            float hA0 = __bfloat162float(__float2bfloat16_rn(pA0));
            float hA1 = __bfloat162float(__float2bfloat16_rn(pA1));
            float hB0 = __bfloat162float(__float2bfloat16_rn(pB0));
            float hB1 = __bfloat162float(__float2bfloat16_rn(pB1));
            *(uint32_t*)(phi + q0 * PT + col) = packbf2(pA0, pA1);
            *(uint32_t*)(plo + q0 * PT + col) = packbf2(pA0 - hA0, pA1 - hA1);
            *(uint32_t*)(phi + (q0 + 8) * PT + col) = packbf2(pB0, pB1);
            *(uint32_t*)(plo + (q0 + 8) * PT + col) = packbf2(pB0 - hB0, pB1 - hB1);
        }
    }

    // load V into the (now free) KV buffers
    for (int rr = 0; rr < 16; rr++) {
        int r = wid * 16 + rr;
        int pos = posk[r];
        const float4* sv = (const float4*)(g_v + ((size_t)(b * T_LEN + pos)) * EMB + h * DH);
        float4 v4 = sv[lane];
        float h0 = __bfloat162float(__float2bfloat16_rn(v4.x));
        float h1 = __bfloat162float(__float2bfloat16_rn(v4.y));
        float h2 = __bfloat162float(__float2bfloat16_rn(v4.z));
        float h3 = __bfloat162float(__float2bfloat16_rn(v4.w));
        uint32_t e = r * PT + lane * 4;
        *(uint2*)(kvhi + e) = make_uint2(packbf2(v4.x, v4.y), packbf2(v4.z, v4.w));
        *(uint2*)(kvlo + e) = make_uint2(packbf2(v4.x - h0, v4.y - h1), packbf2(v4.z - h2, v4.w - h3));
    }
    __syncthreads();

    // phase 4: O[64][128] = P @ V, warp = (mt, dh2): 16q x 64d
    {
        int dh2 = nh;
        float cO[8][4];
#pragma unroll
        for (int i = 0; i < 8; i++)
#pragma unroll
            for (int j = 0; j < 4; j++) cO[i][j] = 0.f;

        uint32_t g = lane >> 3, i2 = lane & 7;
#pragma unroll
        for (int ks = 0; ks < 8; ks++) {
            int k0 = ks * 16;
            uint32_t ah[4], al[4];
            uint32_t aoff = (uint32_t)(((mt * 16 + (lane & 15)) * PT + k0 + ((lane >> 4) << 3)) * 2);
            ldm_x4(ah, sb + OFF_P_HI + aoff);
            ldm_x4(al, sb + OFF_P_LO + aoff);
#pragma unroll
            for (int dp = 0; dp < 4; dp++) {
                int d0 = dh2 * 64 + dp * 16;
                uint32_t boff = (uint32_t)(((k0 + ((g & 1) << 3) + i2) * PT + d0 + ((g >> 1) << 3)) * 2);
                uint32_t bh4[4], bl4[4];
                ldm_x4_t(bh4, sb + OFF_KV_HI + boff);
                ldm_x4_t(bl4, sb + OFF_KV_LO + boff);
                mma16816(cO[dp * 2], ah, bh4);
                mma16816(cO[dp * 2], ah, bl4);
                mma16816(cO[dp * 2], al, bh4);
                mma16816(cO[dp * 2 + 1], ah, bh4 + 2);
                mma16816(cO[dp * 2 + 1], ah, bl4 + 2);
                mma16816(cO[dp * 2 + 1], al, bh4 + 2);
            }
        }
        float* base0 = g_so + ((size_t)bh * HT + c * BUCKETSZ + q0) * DH;
        float* base1 = g_so + ((size_t)bh * HT + c * BUCKETSZ + q0 + 8) * DH;
#pragma unroll
        for (int t8 = 0; t8 < 8; t8++) {
            int d = dh2 * 64 + t8 * 8 + ((lane & 3) << 1);
            *(float2*)(base0 + d) = make_float2(cO[t8][0], cO[t8][1]);
            *(float2*)(base1 + d) = make_float2(cO[t8][2], cO[t8][3]);
        }
    }
}

// ----------------------------- combine hash rounds --------------------------
__global__ void combine_kernel()
{
    int gw = (blockIdx.x * 256 + threadIdx.x) >> 5;
    int lane = threadIdx.x & 31;
    int bh = gw >> 13;
    int pos = gw & (T_LEN - 1);
    int b = bh >> 3, hh = bh & 7;

    int s = 0;
    float l = -1e30f;
    if (lane < N_HASH) {
        s = g_undo[(size_t)bh * HT + (size_t)lane * T_LEN + pos];
        l = g_slog[(size_t)bh * HT + s];
    }
    float m = l;
#pragma unroll
    for (int o = 16; o > 0; o >>= 1) m = fmaxf(m, __shfl_xor_sync(0xffffffffu, m, o));
    float e = (lane < N_HASH) ? expf(l - m) : 0.f;
    float Z = e;
#pragma unroll
    for (int o = 16; o > 0; o >>= 1) Z += __shfl_xor_sync(0xffffffffu, Z, o);

    float4 acc = make_float4(0.f, 0.f, 0.f, 0.f);
#pragma unroll
    for (int h2 = 0; h2 < N_HASH; h2++) {
        int sh = __shfl_sync(0xffffffffu, s, h2);
        float wv = __shfl_sync(0xffffffffu, e, h2) / Z;
        const float4* row = (const float4*)(g_so + ((size_t)bh * HT + sh) * DH);
        float4 t = row[lane];
        acc.x = fmaf(wv, t.x, acc.x);
        acc.y = fmaf(wv, t.y, acc.y);
        acc.z = fmaf(wv, t.z, acc.z);
        acc.w = fmaf(wv, t.w, acc.w);
    }
    size_t off = ((size_t)(b * T_LEN + pos)) * EMB + hh * DH + lane * 4;
    float fv[4] = {acc.x, acc.y, acc.z, acc.w};
    __nv_bfloat16 hi[4]; float lo[4];
#pragma unroll
    for (int u = 0; u < 4; u++) { hi[u] = __float2bfloat16_rn(fv[u]); lo[u] = fv[u] - __bfloat162float(hi[u]); }
    ((__nv_bfloat162*)(g_attn_hi + off))[0] = __nv_bfloat162(hi[0], hi[1]);
    ((__nv_bfloat162*)(g_attn_hi + off))[1] = __nv_bfloat162(hi[2], hi[3]);
    ((__nv_bfloat162*)(g_attn_lo + off))[0] = __floats2bfloat162_rn(lo[0], lo[1]);
    ((__nv_bfloat162*)(g_attn_lo + off))[1] = __floats2bfloat162_rn(lo[2], lo[3]);
}

// ----------------------------- launcher -------------------------------------
extern "C" void kernel_launch(void* const* d_in, const int* in_sizes, int n_in,
                              void* d_out, int out_size)
{
    const float* x = (const float*)d_in[0];
    const unsigned char* pm = (const unsigned char*)d_in[1];
    const float* rot = (const float*)d_in[2];
    const float* Wqk = (const float*)d_in[3];
    const float* Wv = (const float*)d_in[4];
    const float* Wout = (const float*)d_in[5];
    const float* bout = (const float*)d_in[6];
    float* out = (float*)d_out;

    float *qk, *v, *rv;
    __nv_bfloat16 *xhi, *xlo, *athi, *atlo;
    __nv_bfloat16 *wvh, *wvl, *woh, *wol;
    cudaGetSymbolAddress((void**)&qk, g_qk);
    cudaGetSymbolAddress((void**)&v, g_v);
    cudaGetSymbolAddress((void**)&rv, g_rv);
    cudaGetSymbolAddress((void**)&xhi, g_x_hi);
    cudaGetSymbolAddress((void**)&xlo, g_x_lo);
    cudaGetSymbolAddress((void**)&athi, g_attn_hi);
    cudaGetSymbolAddress((void**)&atlo, g_attn_lo);
    cudaGetSymbolAddress((void**)&wvh, g_wvT_hi);
    cudaGetSymbolAddress((void**)&wvl, g_wvT_lo);
    cudaGetSymbolAddress((void**)&woh, g_woutT_hi);
    cudaGetSymbolAddress((void**)&wol, g_woutT_lo);

    cudaFuncSetAttribute(mma_gemm, cudaFuncAttributeMaxDynamicSharedMemorySize, GEMM_SMEM);
    cudaFuncSetAttribute(attn_kernel, cudaFuncAttributeMaxDynamicSharedMemorySize, SMEM_ATT);

    convert_pair_kernel<<<(BT * EMB) / 256, 256>>>(x, xhi, xlo, BT * EMB);
    transpose_pair_kernel<<<dim3(EMB / 32, EMB / 32), dim3(32, 8)>>>(Wv, wvh, wvl, EMB, EMB);
    transpose_pair_kernel<<<dim3(EMB / 32, EMB / 32), dim3(32, 8)>>>(Wout, woh, wol, EMB, EMB);

    // qk = x @ Wqk — EXACT fp32 sequential-k (bucket path)
    gemm_kernel<<<dim3(EMB / GBN, BT / GBM, 1), 256>>>(x, Wqk, qk, nullptr,
        BT, EMB, EMB, EMB, EMB, EMB, 0, 0, 1, 0);
    // v = x @ Wv — tensor cores
    mma_gemm<<<dim3(EMB / 128, BT / 128, 1), 256, GEMM_SMEM>>>(
        xhi, xlo, wvh, wvl, v, nullptr, EMB, EMB, EMB, EMB);
    // rv = qk_head @ rot — EXACT fp32
    gemm_kernel<<<dim3(512 / GBN, T_LEN / GBM, BHD), 256>>>(qk, rot, rv, nullptr,
        T_LEN, 512, DH, EMB, 512, 512,
        (long long)T_LEN * EMB, DH, N_HASH, (long long)T_LEN * 512);

    bucket_kernel<<<(BHD * HT) / 256, 256>>>();
    zero_counts_kernel<<<(BHD * NBTOT + 255) / 256, 256>>>();
    hist_kernel<<<(BHD * HT) / 256, 256>>>();
    scan_kernel<<<BHD, NBTOT>>>();
    scatter_kernel<<<(BHD * N_HASH) / 4, 128>>>();

    attn_kernel<<<dim3(NCHUNK, BHD), 256, SMEM_ATT>>>(pm);

    combine_kernel<<<(BHD * T_LEN) / 8, 256>>>();

    // out = attn @ Wout + bout — tensor cores
    mma_gemm<<<dim3(EMB / 128, BT / 128, 1), 256, GEMM_SMEM>>>(
        athi, atlo, woh, wol, out, bout, EMB, EMB, EMB, EMB);
}

// round 8
// speedup vs baseline: 2.0786x; 1.0598x over previous
#include <cuda_runtime.h>
#include <cuda_bf16.h>
#include <cuda_fp16.h>
#include <cstdint>
#include <math.h>

#define T_LEN   8192
#define B_SZ    2
#define N_HEADS 8
#define DH      128
#define EMB     1024
#define BHD     16          // B * HEADS
#define N_HASH  8
#define NB      128         // buckets per hash
#define NBTOT   1024        // N_HASH * NB
#define BUCKETSZ 64
#define NCHUNK  1024        // per bh
#define HT      65536       // N_HASH * T
#define BT      16384       // B * T
#define QSCALE  0.08838834764831843f
#define FIX_CAP (1 << 20)
#define MARGIN_TH 1e-2f

// ----------------------------- scratch (static device memory; no allocs) ---
__device__ float g_qk[(size_t)BT * EMB];            // fp32 exact (bucket + attention)
__device__ float g_v[(size_t)BT * EMB];
__device__ __half g_x_hi[(size_t)BT * EMB];
__device__ __half g_x_lo[(size_t)BT * EMB];
__device__ __half g_qk_hi[(size_t)BT * EMB];
__device__ __half g_qk_lo[(size_t)BT * EMB];
__device__ __half g_attn_hi[(size_t)BT * EMB];
__device__ __half g_attn_lo[(size_t)BT * EMB];
__device__ __half g_wvT_hi[EMB * EMB];
__device__ __half g_wvT_lo[EMB * EMB];
__device__ __half g_woutT_hi[EMB * EMB];
__device__ __half g_woutT_lo[EMB * EMB];
__device__ __half g_rotT_hi[512 * DH];
__device__ __half g_rotT_lo[512 * DH];
__device__ float g_rv[(size_t)BHD * T_LEN * 512];
__device__ int   g_buckets[(size_t)BHD * HT];
__device__ int   g_counts[BHD * NBTOT];
__device__ int   g_offsets[BHD * NBTOT];
__device__ int   g_st[(size_t)BHD * HT];
__device__ int   g_undo[(size_t)BHD * HT];
__device__ int   g_fixn;
__device__ int   g_fixlist[FIX_CAP];
__device__ float g_so[(size_t)BHD * HT * DH];
__device__ float g_slog[(size_t)BHD * HT];

// ----------------------------- cp.async helpers -----------------------------
__device__ __forceinline__ void cp_async16(uint32_t dst, const void* src) {
    asm volatile("cp.async.ca.shared.global [%0], [%1], 16;" :: "r"(dst), "l"(src));
}
#define CP_COMMIT() asm volatile("cp.async.commit_group;" ::: "memory")
#define CP_WAIT0()  asm volatile("cp.async.wait_group 0;" ::: "memory")

// ----------------------------- exact fp32 GEMM (bucket path: qk) ------------
// 128x128 tile, 2-stage cp.async pipeline. Sequential ascending-k single
// accumulator per output -> bitwise identical to the proven passing kernels.
#define GBM 128
#define GBN 128
#define GBK 16

__global__ void __launch_bounds__(256, 2) gemm_kernel(
    const float* __restrict__ A, const float* __restrict__ Bm,
    float* __restrict__ C,
    __half* __restrict__ Chi, __half* __restrict__ Clo,
    int K, int lda, int ldb, int ldc)
{
    __shared__ float As[2][GBK][GBM + 4];
    __shared__ float Bs[2][GBK][GBN];
    int row0 = blockIdx.y * GBM;
    int col0 = blockIdx.x * GBN;
    int tid = threadIdx.x;
    int tx = tid & 15, ty = tid >> 4;

    float acc[8][8];
#pragma unroll
    for (int i = 0; i < 8; i++)
#pragma unroll
        for (int j = 0; j < 8; j++) acc[i][j] = 0.f;

    float4 areg[2];
#pragma unroll
    for (int i = 0; i < 2; i++) {
        int idx = tid + (i << 8);
        int row = idx >> 2, ks4 = (idx & 3) << 2;
        areg[i] = *(const float4*)&A[(size_t)(row0 + row) * lda + ks4];
    }
#pragma unroll
    for (int i = 0; i < 2; i++) {
        int idx = tid + (i << 8);
        int kk = idx >> 5, c4 = (idx & 31) << 2;
        cp_async16((uint32_t)__cvta_generic_to_shared(&Bs[0][kk][c4]),
                   &Bm[(size_t)kk * ldb + col0 + c4]);
    }
    CP_COMMIT();
#pragma unroll
    for (int i = 0; i < 2; i++) {
        int idx = tid + (i << 8);
        int row = idx >> 2, ks4 = (idx & 3) << 2;
        As[0][ks4 + 0][row] = areg[i].x;
        As[0][ks4 + 1][row] = areg[i].y;
        As[0][ks4 + 2][row] = areg[i].z;
        As[0][ks4 + 3][row] = areg[i].w;
    }
    CP_WAIT0();
    __syncthreads();

    int cur = 0;
    for (int k0 = 0; k0 < K; k0 += GBK) {
        int nxt = cur ^ 1;
        bool has = (k0 + GBK) < K;
        if (has) {
#pragma unroll
            for (int i = 0; i < 2; i++) {
                int idx = tid + (i << 8);
                int row = idx >> 2, ks4 = (idx & 3) << 2;
                areg[i] = *(const float4*)&A[(size_t)(row0 + row) * lda + k0 + GBK + ks4];
            }
#pragma unroll
            for (int i = 0; i < 2; i++) {
                int idx = tid + (i << 8);
                int kk = idx >> 5, c4 = (idx & 31) << 2;
                cp_async16((uint32_t)__cvta_generic_to_shared(&Bs[nxt][kk][c4]),
                           &Bm[(size_t)(k0 + GBK + kk) * ldb + col0 + c4]);
            }
            CP_COMMIT();
        }
#pragma unroll
        for (int kk = 0; kk < GBK; kk++) {
            float4 a0 = *(float4*)&As[cur][kk][ty * 4];
            float4 a1 = *(float4*)&As[cur][kk][64 + ty * 4];
            float4 b0 = *(float4*)&Bs[cur][kk][tx * 4];
            float4 b1 = *(float4*)&Bs[cur][kk][64 + tx * 4];
            float av[8] = {a0.x, a0.y, a0.z, a0.w, a1.x, a1.y, a1.z, a1.w};
            float bv[8] = {b0.x, b0.y, b0.z, b0.w, b1.x, b1.y, b1.z, b1.w};
#pragma unroll
            for (int i = 0; i < 8; i++)
#pragma unroll
                for (int j = 0; j < 8; j++) acc[i][j] = fmaf(av[i], bv[j], acc[i][j]);
        }
        if (has) {
#pragma unroll
            for (int i = 0; i < 2; i++) {
                int idx = tid + (i << 8);
                int row = idx >> 2, ks4 = (idx & 3) << 2;
                As[nxt][ks4 + 0][row] = areg[i].x;
                As[nxt][ks4 + 1][row] = areg[i].y;
                As[nxt][ks4 + 2][row] = areg[i].z;
                As[nxt][ks4 + 3][row] = areg[i].w;
            }
            CP_WAIT0();
        }
        __syncthreads();
        cur = nxt;
    }
#pragma unroll
    for (int ih = 0; ih < 2; ih++)
#pragma unroll
        for (int i = 0; i < 4; i++) {
            int r = row0 + ih * 64 + ty * 4 + i;
#pragma unroll
            for (int jh = 0; jh < 2; jh++) {
                int c = col0 + jh * 64 + tx * 4;
                float4 o;
                o.x = acc[ih * 4 + i][jh * 4 + 0];
                o.y = acc[ih * 4 + i][jh * 4 + 1];
                o.z = acc[ih * 4 + i][jh * 4 + 2];
                o.w = acc[ih * 4 + i][jh * 4 + 3];
                size_t off = (size_t)r * ldc + c;
                *(float4*)&C[off] = o;
                if (Chi) {
                    float fv[4] = {o.x, o.y, o.z, o.w};
                    __half hh[4]; float lo[4];
#pragma unroll
                    for (int u = 0; u < 4; u++) {
                        hh[u] = __float2half_rn(fv[u]);
                        lo[u] = fv[u] - __half2float(hh[u]);
                    }
                    ((__half2*)(Chi + off))[0] = __half2(hh[0], hh[1]);
                    ((__half2*)(Chi + off))[1] = __half2(hh[2], hh[3]);
                    ((__half2*)(Clo + off))[0] = __half2(__float2half_rn(lo[0]), __float2half_rn(lo[1]));
                    ((__half2*)(Clo + off))[1] = __half2(__float2half_rn(lo[2]), __float2half_rn(lo[3]));
                }
            }
        }
}

// ----------------------------- mma helpers (portable PTX, sm_80+) ----------
__device__ __forceinline__ uint32_t smem_u32(const void* p) {
    uint32_t a;
    asm("{ .reg .u64 t; cvta.to.shared.u64 t, %1; cvt.u32.u64 %0, t; }" : "=r"(a) : "l"(p));
    return a;
}
__device__ __forceinline__ void ldm_x4(uint32_t* r, uint32_t addr) {
    asm volatile("ldmatrix.sync.aligned.m8n8.x4.shared.b16 {%0,%1,%2,%3}, [%4];"
        : "=r"(r[0]), "=r"(r[1]), "=r"(r[2]), "=r"(r[3]) : "r"(addr));
}
__device__ __forceinline__ void ldm_x4_t(uint32_t* r, uint32_t addr) {
    asm volatile("ldmatrix.sync.aligned.m8n8.x4.trans.shared.b16 {%0,%1,%2,%3}, [%4];"
        : "=r"(r[0]), "=r"(r[1]), "=r"(r[2]), "=r"(r[3]) : "r"(addr));
}
__device__ __forceinline__ void ldm_x2(uint32_t* r, uint32_t addr) {
    asm volatile("ldmatrix.sync.aligned.m8n8.x2.shared.b16 {%0,%1}, [%2];"
        : "=r"(r[0]), "=r"(r[1]) : "r"(addr));
}
__device__ __forceinline__ void mma16816(float* d, const uint32_t* a, const uint32_t* b) {
    asm volatile("mma.sync.aligned.m16n8k16.row.col.f32.bf16.bf16.f32 "
        "{%0,%1,%2,%3}, {%4,%5,%6,%7}, {%8,%9}, {%0,%1,%2,%3};"
        : "+f"(d[0]), "+f"(d[1]), "+f"(d[2]), "+f"(d[3])
        : "r"(a[0]), "r"(a[1]), "r"(a[2]), "r"(a[3]), "r"(b[0]), "r"(b[1]));
}
__device__ __forceinline__ void mma16816h(float* d, const uint32_t* a, const uint32_t* b) {
    asm volatile("mma.sync.aligned.m16n8k16.row.col.f32.f16.f16.f32 "
        "{%0,%1,%2,%3}, {%4,%5,%6,%7}, {%8,%9}, {%0,%1,%2,%3};"
        : "+f"(d[0]), "+f"(d[1]), "+f"(d[2]), "+f"(d[3])
        : "r"(a[0]), "r"(a[1]), "r"(a[2]), "r"(a[3]), "r"(b[0]), "r"(b[1]));
}
__device__ __forceinline__ uint32_t packbf2(float x, float y) {
    __nv_bfloat162 p(__float2bfloat16_rn(x), __float2bfloat16_rn(y));
    return *(uint32_t*)&p;
}

// ----------------------------- fp16-split tensor-core GEMM ------------------
#define SA_HI 0
#define SA_LO 16384
#define SB_HI 32768
#define SB_LO 49152
#define GEMM_SMEM 65536

template<int TERMS>
__global__ void __launch_bounds__(256) mma_gemm_h(
    const __half* __restrict__ Ahi, const __half* __restrict__ Alo,
    const __half* __restrict__ Bhi, const __half* __restrict__ Blo,
    float* __restrict__ C, const float* __restrict__ bias,
    int K, int lda, int ldb, int ldc,
    long long sAouter, long long sAinner, int innerDiv,
    long long sB, long long sC)
{
    extern __shared__ char sm[];
    uint32_t sb = smem_u32(sm);
    int tid = threadIdx.x, lane = tid & 31, wid = tid >> 5;
    int wm = wid & 1, wn = wid >> 1;

    long long z = blockIdx.z;
    size_t aoff = (size_t)((z / innerDiv) * sAouter + (z % innerDiv) * sAinner);
    const __half* Ah = Ahi + aoff;
    const __half* Al = Alo + aoff;
    const __half* Bh = Bhi + (size_t)(z * sB);
    const __half* Bl = Blo + (size_t)(z * sB);
    float* Cb = C + (size_t)(z * sC);
    int m0 = blockIdx.y * 128, n0 = blockIdx.x * 128;

    float acc[4][4][4];
#pragma unroll
    for (int mt = 0; mt < 4; mt++)
#pragma unroll
        for (int nt = 0; nt < 4; nt++)
#pragma unroll
            for (int i = 0; i < 4; i++) acc[mt][nt][i] = 0.f;

    int nch = K >> 6;
    for (int ch = 0; ch < nch; ch++) {
        int k0 = ch << 6;
        const __half* Abh = Ah + (size_t)m0 * lda + k0;
        const __half* Abl = Al + (size_t)m0 * lda + k0;
        const __half* Bbh = Bh + (size_t)n0 * ldb + k0;
        const __half* Bbl = Bl + (size_t)n0 * ldb + k0;
#pragma unroll
        for (int i = 0; i < 4; i++) {
            int idx = tid + (i << 8);
            int row = idx >> 3, seg = idx & 7;
            uint32_t off = (uint32_t)((row << 7) + (seg << 4));
            uint32_t sw = off ^ ((off >> 3) & 0x70);
            *(uint4*)(sm + SA_HI + sw) = *(const uint4*)(Abh + (size_t)row * lda + (seg << 3));
            *(uint4*)(sm + SA_LO + sw) = *(const uint4*)(Abl + (size_t)row * lda + (seg << 3));
            *(uint4*)(sm + SB_HI + sw) = *(const uint4*)(Bbh + (size_t)row * ldb + (seg << 3));
            *(uint4*)(sm + SB_LO + sw) = *(const uint4*)(Bbl + (size_t)row * ldb + (seg << 3));
        }
        __syncthreads();
#pragma unroll
        for (int kk = 0; kk < 4; kk++) {
            uint32_t afh[4][4], afl[4][4];
#pragma unroll
            for (int mt = 0; mt < 4; mt++) {
                int row = wm * 64 + mt * 16 + (lane & 15);
                uint32_t off = (uint32_t)((row << 7) + (kk << 5) + ((lane >> 4) << 4));
                uint32_t sw = off ^ ((off >> 3) & 0x70);
                ldm_x4(afh[mt], sb + SA_HI + sw);
                ldm_x4(afl[mt], sb + SA_LO + sw);
            }
            uint32_t bfh[4][2], bfl[4][2];
#pragma unroll
            for (int nt = 0; nt < 4; nt++) {
                int row = wn * 32 + nt * 8 + (lane & 7);
                uint32_t off = (uint32_t)((row << 7) + (kk << 5) + (((lane >> 3) & 1) << 4));
                uint32_t sw = off ^ ((off >> 3) & 0x70);
                ldm_x2(bfh[nt], sb + SB_HI + sw);
                ldm_x2(bfl[nt], sb + SB_LO + sw);
            }
#pragma unroll
            for (int mt = 0; mt < 4; mt++)
#pragma unroll
                for (int nt = 0; nt < 4; nt++) {
                    mma16816h(acc[mt][nt], afh[mt], bfh[nt]);
                    mma16816h(acc[mt][nt], afh[mt], bfl[nt]);
                    mma16816h(acc[mt][nt], afl[mt], bfh[nt]);
                    if (TERMS == 4) mma16816h(acc[mt][nt], afl[mt], bfl[nt]);
                }
        }
        __syncthreads();
    }

#pragma unroll
    for (int mt = 0; mt < 4; mt++) {
#pragma unroll
        for (int nt = 0; nt < 4; nt++) {
            int c = n0 + wn * 32 + nt * 8 + ((lane & 3) << 1);
#pragma unroll
            for (int half = 0; half < 2; half++) {
                int r = m0 + wm * 64 + mt * 16 + (lane >> 2) + half * 8;
                float v0 = acc[mt][nt][half * 2 + 0];
                float v1 = acc[mt][nt][half * 2 + 1];
                if (bias) { v0 += bias[c]; v1 += bias[c + 1]; }
                *(float2*)(Cb + (size_t)r * ldc + c) = make_float2(v0, v1);
            }
        }
    }
}

// ----------------------------- conversions ----------------------------------
__global__ void convert_pair_kernel(const float* __restrict__ src,
                                    __half* __restrict__ hi,
                                    __half* __restrict__ lo, int n)
{
    int i = blockIdx.x * 256 + threadIdx.x;
    if (i < n) {
        float v = src[i];
        __half h = __float2half_rn(v);
        hi[i] = h;
        lo[i] = __float2half_rn(v - __half2float(h));
    }
}

__global__ void transpose_pair_kernel(const float* __restrict__ src,
                                      __half* __restrict__ dhi,
                                      __half* __restrict__ dlo, int R, int C)
{
    __shared__ float t[32][33];
    int c0 = blockIdx.x * 32, r0 = blockIdx.y * 32;
    int x = threadIdx.x, y = threadIdx.y;
    for (int i = 0; i < 32; i += 8)
        t[y + i][x] = src[(size_t)(r0 + y + i) * C + c0 + x];
    __syncthreads();
    for (int i = 0; i < 32; i += 8) {
        float v = t[x][y + i];
        __half h = __float2half_rn(v);
        size_t o = (size_t)(c0 + y + i) * R + r0 + x;
        dhi[o] = h;
        dlo[o] = __float2half_rn(v - __half2float(h));
    }
}

// ----------------------------- bucket argmax + margin guard -----------------
__global__ void bucket_kernel()
{
    int idx = blockIdx.x * 256 + threadIdx.x;
    int h = idx & 7;
    int t = (idx >> 3) & (T_LEN - 1);
    int bh = idx >> 16;
    const float4* p = (const float4*)(g_rv + ((size_t)bh * T_LEN + t) * 512 + h * 64);
    float max1 = -1e30f, max2 = -1e30f, min1 = 1e30f, min2 = 1e30f;
    int imax = 0, imin = 0;
#pragma unroll
    for (int i = 0; i < 16; i++) {
        float4 q = p[i];
        float vv[4] = {q.x, q.y, q.z, q.w};
#pragma unroll
        for (int c = 0; c < 4; c++) {
            int j = i * 4 + c;
            float v = vv[c];
            if (v > max1) { max2 = max1; max1 = v; imax = j; }
            else if (v > max2) max2 = v;
            if (v < min1) { min2 = min1; min1 = v; imin = j; }
            else if (v < min2) min2 = v;
        }
    }
    float best, second;
    int bi;
    if (max1 >= -min1) { best = max1; bi = imax; second = fmaxf(max2, -min1); }
    else               { best = -min1; bi = 64 + imin; second = fmaxf(max1, -min2); }
    g_buckets[(size_t)bh * HT + (size_t)h * T_LEN + t] = bi + h * NB;
    if (best - second < MARGIN_TH) {
        int slot = atomicAdd(&g_fixn, 1);
        if (slot < FIX_CAP)
            g_fixlist[slot] = (bh << 16) | (h * T_LEN + t);
    }
}

// exact sequential-fp32 recompute of flagged rows (one warp per entry)
__global__ void fixup_kernel(const float* __restrict__ rot)
{
    int gw = (blockIdx.x * 256 + threadIdx.x) >> 5;
    int lane = threadIdx.x & 31;
    int nwarps = gridDim.x * 8;
    int n = g_fixn;
    if (n > FIX_CAP) n = FIX_CAP;
    for (int e = gw; e < n; e += nwarps) {
        int ent = g_fixlist[e];
        int bh = ent >> 16;
        int ht = ent & 65535;
        int h = ht >> 13, t = ht & (T_LEN - 1);
        int b = bh >> 3, hh = bh & 7;
        const float* qrow = g_qk + ((size_t)(b * T_LEN + t)) * EMB + hh * DH;
        int c1 = lane, c2 = lane + 32;
        float r1 = 0.f, r2 = 0.f;
        for (int k = 0; k < DH; k++) {
            float a = qrow[k];
            const float* rp = rot + ((size_t)k * 8 + h) * 64;
            r1 = fmaf(a, rp[c1], r1);
            r2 = fmaf(a, rp[c2], r2);
        }
        // first-max over candidates [rv(0..63), -rv(64..127)] in index order
        float best = r1; int bi = c1;
        if (r2 > best)  { best = r2;  bi = c2; }
        if (-r1 > best) { best = -r1; bi = 64 + c1; }
        if (-r2 > best) { best = -r2; bi = 64 + c2; }
#pragma unroll
        for (int o = 16; o > 0; o >>= 1) {
            float ov = __shfl_xor_sync(0xffffffffu, best, o);
            int oi = __shfl_xor_sync(0xffffffffu, bi, o);
            if (ov > best || (ov == best && oi < bi)) { best = ov; bi = oi; }
        }
        if (lane == 0)
            g_buckets[(size_t)bh * HT + (size_t)h * T_LEN + t] = bi + h * NB;
    }
}

__global__ void zero_counts_kernel()
{
    int idx = blockIdx.x * 256 + threadIdx.x;
    if (idx < BHD * NBTOT) g_counts[idx] = 0;
    if (idx == 0) g_fixn = 0;
}

__global__ void hist_kernel()
{
    int idx = blockIdx.x * 256 + threadIdx.x;
    int bh = idx >> 16;
    atomicAdd(&g_counts[bh * NBTOT + g_buckets[idx]], 1);
}

__global__ void scan_kernel()
{
    __shared__ int s[NBTOT];
    int bh = blockIdx.x, t = threadIdx.x;
    int my = g_counts[bh * NBTOT + t];
    s[t] = my;
    __syncthreads();
    for (int d = 1; d < NBTOT; d <<= 1) {
        int v = (t >= d) ? s[t - d] : 0;
        __syncthreads();
        s[t] += v;
        __syncthreads();
    }
    g_offsets[bh * NBTOT + t] = s[t] - my;
}

__global__ void scatter_kernel()
{
    __shared__ int cnt[4][NB];
    int w = threadIdx.x >> 5, lane = threadIdx.x & 31;
    int wg = blockIdx.x * 4 + w;
    int bh = wg >> 3, h = wg & 7;
#pragma unroll
    for (int i = 0; i < 4; i++)
        cnt[w][lane * 4 + i] = g_offsets[bh * NBTOT + h * NB + lane * 4 + i];
    __syncwarp();
    const int* bk = g_buckets + (size_t)bh * HT + (size_t)h * T_LEN;
    int* stp = g_st + (size_t)bh * HT;
    int* unp = g_undo + (size_t)bh * HT + (size_t)h * T_LEN;
    for (int t0 = 0; t0 < T_LEN; t0 += 32) {
        int t = t0 + lane;
        int b = bk[t] - h * NB;
        unsigned mask = __match_any_sync(0xffffffffu, b);
        int lead = __ffs(mask) - 1;
        int pre = __popc(mask & ((1u << lane) - 1u));
        int base = 0;
        if (lane == lead) base = cnt[w][b];
        base = __shfl_sync(0xffffffffu, base, lead);
        int rnk = base + pre;
        if (lane == lead) cnt[w][b] = base + __popc(mask);
        stp[rnk] = t;
        unp[t] = rnk;
        __syncwarp();
    }
}

// ----------------------------- tensor-core chunked attention ----------------
#define PT  136
#define OFF_KV_HI 0
#define OFF_KV_LO 34816
#define OFF_P_HI  69632
#define OFF_P_LO  87040
#define OFF_REDM  104448
#define OFF_REDS  104960
#define OFF_POS   105472
#define OFF_PAD   105984
#define SMEM_ATT  106496

__global__ void __launch_bounds__(256, 2) attn_kernel(const unsigned char* __restrict__ pm)
{
    extern __shared__ char sm[];
    uint32_t sb = smem_u32(sm);
    __nv_bfloat16* kvhi = (__nv_bfloat16*)(sm + OFF_KV_HI);
    __nv_bfloat16* kvlo = (__nv_bfloat16*)(sm + OFF_KV_LO);
    __nv_bfloat16* phi = (__nv_bfloat16*)(sm + OFF_P_HI);
    __nv_bfloat16* plo = (__nv_bfloat16*)(sm + OFF_P_LO);
    float* redM = (float*)(sm + OFF_REDM);
    float* redS = (float*)(sm + OFF_REDS);
    int* posk = (int*)(sm + OFF_POS);
    int* padk = (int*)(sm + OFF_PAD);

    int bh = blockIdx.y, c = blockIdx.x;
    int b = bh >> 3, h = bh & 7;
    int tid = threadIdx.x, lane = tid & 31, wid = tid >> 5;

    if (tid < 128) {
        int j = tid;
        int cprev = (c == 0) ? (NCHUNK - 1) : (c - 1);
        int slot = (j < BUCKETSZ) ? c * BUCKETSZ + j : cprev * BUCKETSZ + (j - BUCKETSZ);
        int pos = g_st[(size_t)bh * HT + slot];
        posk[j] = pos;
        padk[j] = pm[b * T_LEN + pos] ? 1 : 0;
    }
    __syncthreads();

    for (int rr = 0; rr < 16; rr++) {
        int r = wid * 16 + rr;
        int pos = posk[r];
        const float4* src = (const float4*)(g_qk + ((size_t)(b * T_LEN + pos)) * EMB + h * DH);
        float4 q4 = src[lane];
        float ss = q4.x * q4.x + q4.y * q4.y + q4.z * q4.z + q4.w * q4.w;
#pragma unroll
        for (int o = 16; o > 0; o >>= 1) ss += __shfl_xor_sync(0xffffffffu, ss, o);
        float rn = rsqrtf(fmaxf(ss, 1e-12f));
        {
            float k0v = q4.x * rn, k1v = q4.y * rn, k2v = q4.z * rn, k3v = q4.w * rn;
            float h0 = __bfloat162float(__float2bfloat16_rn(k0v));
            float h1 = __bfloat162float(__float2bfloat16_rn(k1v));
            float h2 = __bfloat162float(__float2bfloat16_rn(k2v));
            float h3 = __bfloat162float(__float2bfloat16_rn(k3v));
            uint32_t e = r * PT + lane * 4;
            *(uint2*)(kvhi + e) = make_uint2(packbf2(k0v, k1v), packbf2(k2v, k3v));
            *(uint2*)(kvlo + e) = make_uint2(packbf2(k0v - h0, k1v - h1), packbf2(k2v - h2, k3v - h3));
        }
        if (r < 64) {
            float q0 = q4.x * QSCALE, q1 = q4.y * QSCALE, q2 = q4.z * QSCALE, q3 = q4.w * QSCALE;
            float h0 = __bfloat162float(__float2bfloat16_rn(q0));
            float h1 = __bfloat162float(__float2bfloat16_rn(q1));
            float h2 = __bfloat162float(__float2bfloat16_rn(q2));
            float h3 = __bfloat162float(__float2bfloat16_rn(q3));
            uint32_t e = r * PT + lane * 4;
            *(uint2*)(phi + e) = make_uint2(packbf2(q0, q1), packbf2(q2, q3));
            *(uint2*)(plo + e) = make_uint2(packbf2(q0 - h0, q1 - h1), packbf2(q2 - h2, q3 - h3));
        }
    }
    __syncthreads();

    int mt = wid & 3, nh = wid >> 2;
    float cS[8][4];
#pragma unroll
    for (int i = 0; i < 8; i++)
#pragma unroll
        for (int j = 0; j < 4; j++) cS[i][j] = 0.f;
    {
        uint32_t g = lane >> 3, i2 = lane & 7;
#pragma unroll
        for (int ks = 0; ks < 8; ks++) {
            int k0 = ks * 16;
            uint32_t ah[4], al[4];
            uint32_t aoff = (uint32_t)(((mt * 16 + (lane & 15)) * PT + k0 + ((lane >> 4) << 3)) * 2);
            ldm_x4(ah, sb + OFF_P_HI + aoff);
            ldm_x4(al, sb + OFF_P_LO + aoff);
#pragma unroll
            for (int np = 0; np < 4; np++) {
                int n0 = nh * 64 + np * 16;
                uint32_t boff = (uint32_t)(((n0 + ((g >> 1) << 3) + i2) * PT + k0 + ((g & 1) << 3)) * 2);
                uint32_t bh4[4], bl4[4];
                ldm_x4(bh4, sb + OFF_KV_HI + boff);
                ldm_x4(bl4, sb + OFF_KV_LO + boff);
                mma16816(cS[np * 2], ah, bh4);
                mma16816(cS[np * 2], ah, bl4);
                mma16816(cS[np * 2], al, bh4);
                mma16816(cS[np * 2 + 1], ah, bh4 + 2);
                mma16816(cS[np * 2 + 1], ah, bl4 + 2);
                mma16816(cS[np * 2 + 1], al, bh4 + 2);
            }
        }
    }

    int q0 = mt * 16 + (lane >> 2);
    {
        int pq0 = posk[q0], pq1 = posk[q0 + 8];
#pragma unroll
        for (int t8 = 0; t8 < 8; t8++) {
            int kvb = nh * 64 + t8 * 8 + ((lane & 3) << 1);
#pragma unroll
            for (int e = 0; e < 2; e++) {
                int kv = kvb + e;
                int pk = posk[kv], pd = padk[kv];
                cS[t8][e]     = (pq0 == pk) ? -1e5f : (pd ? -1e9f : cS[t8][e]);
                cS[t8][2 + e] = (pq1 == pk) ? -1e5f : (pd ? -1e9f : cS[t8][2 + e]);
            }
        }
    }

    float lseA, lseB;
    {
        float mA = -1e30f, mB = -1e30f;
#pragma unroll
        for (int t8 = 0; t8 < 8; t8++) {
            mA = fmaxf(mA, fmaxf(cS[t8][0], cS[t8][1]));
            mB = fmaxf(mB, fmaxf(cS[t8][2], cS[t8][3]));
        }
        mA = fmaxf(mA, __shfl_xor_sync(0xffffffffu, mA, 1));
        mA = fmaxf(mA, __shfl_xor_sync(0xffffffffu, mA, 2));
        mB = fmaxf(mB, __shfl_xor_sync(0xffffffffu, mB, 1));
        mB = fmaxf(mB, __shfl_xor_sync(0xffffffffu, mB, 2));
        if ((lane & 3) == 0) {
            redM[q0 * 2 + nh] = mA;
            redM[(q0 + 8) * 2 + nh] = mB;
        }
        __syncthreads();
        float MA = fmaxf(redM[q0 * 2], redM[q0 * 2 + 1]);
        float MB = fmaxf(redM[(q0 + 8) * 2], redM[(q0 + 8) * 2 + 1]);
        float sA = 0.f, sB = 0.f;
#pragma unroll
        for (int t8 = 0; t8 < 8; t8++) {
            sA += __expf(cS[t8][0] - MA) + __expf(cS[t8][1] - MA);
            sB += __expf(cS[t8][2] - MB) + __expf(cS[t8][3] - MB);
        }
        sA += __shfl_xor_sync(0xffffffffu, sA, 1);
        sA += __shfl_xor_sync(0xffffffffu, sA, 2);
        sB += __shfl_xor_sync(0xffffffffu, sB, 1);
        sB += __shfl_xor_sync(0xffffffffu, sB, 2);
        if ((lane & 3) == 0) {
            redS[q0 * 2 + nh] = sA;
            redS[(q0 + 8) * 2 + nh] = sB;
        }
        __syncthreads();
        float ZA = redS[q0 * 2] + redS[q0 * 2 + 1];
        float ZB = redS[(q0 + 8) * 2] + redS[(q0 + 8) * 2 + 1];
        lseA = MA + logf(ZA);
        lseB = MB + logf(ZB);
        if (nh == 0 && (lane & 3) == 0) {
            g_slog[(size_t)bh * HT + c * BUCKETSZ + q0] = lseA;
            g_slog[(size_t)bh * HT + c * BUCKETSZ + q0 + 8] = lseB;
        }
#pragma unroll
        for (int t8 = 0; t8 < 8; t8++) {
            int col = nh * 64 + t8 * 8 + ((lane & 3) << 1);
            float pA0 = __expf(cS[t8][0] - lseA), pA1 = __expf(cS[t8][1] - lseA);
            float pB0 = __expf(cS[t8][2] - lseB), pB1 = __expf(cS[t8][3] - lseB);
            float hA0 = __bfloat162float(__float2bfloat16_rn(pA0));
            float hA1 = __bfloat162float(__float2bfloat16_rn(pA1));
            float hB0 = __bfloat162float(__float2bfloat16_rn(pB0));
            float hB1 = __bfloat162float(__float2bfloat16_rn(pB1));
            *(uint32_t*)(phi + q0 * PT + col) = packbf2(pA0, pA1);
            *(uint32_t*)(plo + q0 * PT + col) = packbf2(pA0 - hA0, pA1 - hA1);
            *(uint32_t*)(phi + (q0 + 8) * PT + col) = packbf2(pB0, pB1);
            *(uint32_t*)(plo + (q0 + 8) * PT + col) = packbf2(pB0 - hB0, pB1 - hB1);
        }
    }

    for (int rr = 0; rr < 16; rr++) {
        int r = wid * 16 + rr;
        int pos = posk[r];
        const float4* sv = (const float4*)(g_v + ((size_t)(b * T_LEN + pos)) * EMB + h * DH);
        float4 v4 = sv[lane];
        float h0 = __bfloat162float(__float2bfloat16_rn(v4.x));
        float h1 = __bfloat162float(__float2bfloat16_rn(v4.y));
        float h2 = __bfloat162float(__float2bfloat16_rn(v4.z));
        float h3 = __bfloat162float(__float2bfloat16_rn(v4.w));
        uint32_t e = r * PT + lane * 4;
        *(uint2*)(kvhi + e) = make_uint2(packbf2(v4.x, v4.y), packbf2(v4.z, v4.w));
        *(uint2*)(kvlo + e) = make_uint2(packbf2(v4.x - h0, v4.y - h1), packbf2(v4.z - h2, v4.w - h3));
    }
    __syncthreads();

    {
        int dh2 = nh;
        float cO[8][4];
#pragma unroll
        for (int i = 0; i < 8; i++)
#pragma unroll
            for (int j = 0; j < 4; j++) cO[i][j] = 0.f;

        uint32_t g = lane >> 3, i2 = lane & 7;
#pragma unroll
        for (int ks = 0; ks < 8; ks++) {
            int k0 = ks * 16;
            uint32_t ah[4], al[4];
            uint32_t aoff = (uint32_t)(((mt * 16 + (lane & 15)) * PT + k0 + ((lane >> 4) << 3)) * 2);
            ldm_x4(ah, sb + OFF_P_HI + aoff);
            ldm_x4(al, sb + OFF_P_LO + aoff);
#pragma unroll
            for (int dp = 0; dp < 4; dp++) {
                int d0 = dh2 * 64 + dp * 16;
                uint32_t boff = (uint32_t)(((k0 + ((g & 1) << 3) + i2) * PT + d0 + ((g >> 1) << 3)) * 2);
                uint32_t bh4[4], bl4[4];
                ldm_x4_t(bh4, sb + OFF_KV_HI + boff);
                ldm_x4_t(bl4, sb + OFF_KV_LO + boff);
                mma16816(cO[dp * 2], ah, bh4);
                mma16816(cO[dp * 2], ah, bl4);
                mma16816(cO[dp * 2], al, bh4);
                mma16816(cO[dp * 2 + 1], ah, bh4 + 2);
                mma16816(cO[dp * 2 + 1], ah, bl4 + 2);
                mma16816(cO[dp * 2 + 1], al, bh4 + 2);
            }
        }
        float* base0 = g_so + ((size_t)bh * HT + c * BUCKETSZ + q0) * DH;
        float* base1 = g_so + ((size_t)bh * HT + c * BUCKETSZ + q0 + 8) * DH;
#pragma unroll
        for (int t8 = 0; t8 < 8; t8++) {
            int d = dh2 * 64 + t8 * 8 + ((lane & 3) << 1);
            *(float2*)(base0 + d) = make_float2(cO[t8][0], cO[t8][1]);
            *(float2*)(base1 + d) = make_float2(cO[t8][2], cO[t8][3]);
        }
    }
}

// ----------------------------- combine hash rounds --------------------------
__global__ void combine_kernel()
{
    int gw = (blockIdx.x * 256 + threadIdx.x) >> 5;
    int lane = threadIdx.x & 31;
    int bh = gw >> 13;
    int pos = gw & (T_LEN - 1);
    int b = bh >> 3, hh = bh & 7;

    int s = 0;
    float l = -1e30f;
    if (lane < N_HASH) {
        s = g_undo[(size_t)bh * HT + (size_t)lane * T_LEN + pos];
        l = g_slog[(size_t)bh * HT + s];
    }
    float m = l;
#pragma unroll
    for (int o = 16; o > 0; o >>= 1) m = fmaxf(m, __shfl_xor_sync(0xffffffffu, m, o));
    float e = (lane < N_HASH) ? expf(l - m) : 0.f;
    float Z = e;
#pragma unroll
    for (int o = 16; o > 0; o >>= 1) Z += __shfl_xor_sync(0xffffffffu, Z, o);

    float4 acc = make_float4(0.f, 0.f, 0.f, 0.f);
#pragma unroll
    for (int h2 = 0; h2 < N_HASH; h2++) {
        int sh = __shfl_sync(0xffffffffu, s, h2);
        float wv = __shfl_sync(0xffffffffu, e, h2) / Z;
        const float4* row = (const float4*)(g_so + ((size_t)bh * HT + sh) * DH);
        float4 t = row[lane];
        acc.x = fmaf(wv, t.x, acc.x);
        acc.y = fmaf(wv, t.y, acc.y);
        acc.z = fmaf(wv, t.z, acc.z);
        acc.w = fmaf(wv, t.w, acc.w);
    }
    size_t off = ((size_t)(b * T_LEN + pos)) * EMB + hh * DH + lane * 4;
    float fv[4] = {acc.x, acc.y, acc.z, acc.w};
    __half hi[4]; float lo[4];
#pragma unroll
    for (int u = 0; u < 4; u++) { hi[u] = __float2half_rn(fv[u]); lo[u] = fv[u] - __half2float(hi[u]); }
    ((__half2*)(g_attn_hi + off))[0] = __half2(hi[0], hi[1]);
    ((__half2*)(g_attn_hi + off))[1] = __half2(hi[2], hi[3]);
    ((__half2*)(g_attn_lo + off))[0] = __half2(__float2half_rn(lo[0]), __float2half_rn(lo[1]));
    ((__half2*)(g_attn_lo + off))[1] = __half2(__float2half_rn(lo[2]), __float2half_rn(lo[3]));
}

// ----------------------------- launcher -------------------------------------
extern "C" void kernel_launch(void* const* d_in, const int* in_sizes, int n_in,
                              void* d_out, int out_size)
{
    const float* x = (const float*)d_in[0];
    const unsigned char* pm = (const unsigned char*)d_in[1];
    const float* rot = (const float*)d_in[2];
    const float* Wqk = (const float*)d_in[3];
    const float* Wv = (const float*)d_in[4];
    const float* Wout = (const float*)d_in[5];
    const float* bout = (const float*)d_in[6];
    float* out = (float*)d_out;

    float *qk, *v, *rv;
    __half *xhi, *xlo, *qkhi, *qklo, *athi, *atlo;
    __half *wvh, *wvl, *woh, *wol, *rth, *rtl;
    cudaGetSymbolAddress((void**)&qk, g_qk);
    cudaGetSymbolAddress((void**)&v, g_v);
    cudaGetSymbolAddress((void**)&rv, g_rv);
    cudaGetSymbolAddress((void**)&xhi, g_x_hi);
    cudaGetSymbolAddress((void**)&xlo, g_x_lo);
    cudaGetSymbolAddress((void**)&qkhi, g_qk_hi);
    cudaGetSymbolAddress((void**)&qklo, g_qk_lo);
    cudaGetSymbolAddress((void**)&athi, g_attn_hi);
    cudaGetSymbolAddress((void**)&atlo, g_attn_lo);
    cudaGetSymbolAddress((void**)&wvh, g_wvT_hi);
    cudaGetSymbolAddress((void**)&wvl, g_wvT_lo);
    cudaGetSymbolAddress((void**)&woh, g_woutT_hi);
    cudaGetSymbolAddress((void**)&wol, g_woutT_lo);
    cudaGetSymbolAddress((void**)&rth, g_rotT_hi);
    cudaGetSymbolAddress((void**)&rtl, g_rotT_lo);

    cudaFuncSetAttribute(mma_gemm_h<3>, cudaFuncAttributeMaxDynamicSharedMemorySize, GEMM_SMEM);
    cudaFuncSetAttribute(mma_gemm_h<4>, cudaFuncAttributeMaxDynamicSharedMemorySize, GEMM_SMEM);
    cudaFuncSetAttribute(attn_kernel, cudaFuncAttributeMaxDynamicSharedMemorySize, SMEM_ATT);

    convert_pair_kernel<<<(BT * EMB) / 256, 256>>>(x, xhi, xlo, BT * EMB);
    transpose_pair_kernel<<<dim3(EMB / 32, EMB / 32), dim3(32, 8)>>>(Wv, wvh, wvl, EMB, EMB);
    transpose_pair_kernel<<<dim3(EMB / 32, EMB / 32), dim3(32, 8)>>>(Wout, woh, wol, EMB, EMB);
    transpose_pair_kernel<<<dim3(512 / 32, DH / 32), dim3(32, 8)>>>(rot, rth, rtl, DH, 512);
    zero_counts_kernel<<<(BHD * NBTOT + 255) / 256, 256>>>();

    // qk = x @ Wqk — EXACT fp32 (bucket path), + fp16-pair output for rv GEMM
    gemm_kernel<<<dim3(EMB / GBN, BT / GBM, 1), 256>>>(x, Wqk, qk, qkhi, qklo,
        EMB, EMB, EMB, EMB);
    // v = x @ Wv — 3-term fp16 tensor (smooth)
    mma_gemm_h<3><<<dim3(EMB / 128, BT / 128, 1), 256, GEMM_SMEM>>>(
        xhi, xlo, wvh, wvl, v, nullptr, EMB, EMB, EMB, EMB, 0, 0, 1, 0, 0);
    // rv[bh] = qk_head[bh] @ rot — 4-term fp16 tensor; margin-guarded below
    mma_gemm_h<4><<<dim3(512 / 128, T_LEN / 128, BHD), 256, GEMM_SMEM>>>(
        qkhi, qklo, rth, rtl, rv, nullptr,
        DH, EMB, DH, 512, (long long)T_LEN * EMB, DH, N_HASH, 0, (long long)T_LEN * 512);

    bucket_kernel<<<(BHD * HT) / 256, 256>>>();
    fixup_kernel<<<256, 256>>>(rot);
    hist_kernel<<<(BHD * HT) / 256, 256>>>();
    scan_kernel<<<BHD, NBTOT>>>();
    scatter_kernel<<<(BHD * N_HASH) / 4, 128>>>();

    attn_kernel<<<dim3(NCHUNK, BHD), 256, SMEM_ATT>>>(pm);

    combine_kernel<<<(BHD * T_LEN) / 8, 256>>>();

    // out = attn @ Wout + bout — 3-term fp16 tensor (smooth)
    mma_gemm_h<3><<<dim3(EMB / 128, BT / 128, 1), 256, GEMM_SMEM>>>(
        athi, atlo, woh, wol, out, bout, EMB, EMB, EMB, EMB, 0, 0, 1, 0, 0);
}